// round 2
// baseline (speedup 1.0000x reference)
#include <cuda_runtime.h>
#include <math.h>

#define HDIM 2048
#define SQ   2048
#define NHEAD 32
#define NKVH  8
#define HD    64
#define IDIM  4096
#define NE    8

// ------------------------- scratch (static, no allocs) -------------------------
__device__ float g_xn1[SQ*HDIM];
__device__ float g_q[SQ*NHEAD*HD];
__device__ float g_k[SQ*NKVH*HD];
__device__ float g_v[SQ*NKVH*HD];
__device__ float g_ctx[SQ*NHEAD*HD];
__device__ float g_resid1[SQ*HDIM];
__device__ float g_xn2[SQ*HDIM];
__device__ float g_rlog[SQ*NE];
__device__ int   g_tok2e[SQ*2];
__device__ float g_tok2w[SQ*2];
__device__ int   g_tok2row[SQ*2];
__device__ int   g_rows[SQ*2];
__device__ int   g_cnt[NE];
__device__ int   g_off[NE+1];
__device__ int   g_cur[NE];
__device__ float g_xg[SQ*2*HDIM];
__device__ float g_b1[SQ*2*IDIM];
__device__ float g_b3[SQ*2*IDIM];
__device__ float g_y[SQ*2*HDIM];
__device__ int   g_pos64;
__device__ float g_posf[SQ];

// ------------------------- position width detection -------------------------
// JAX without x64 silently downcasts int64 -> int32. Detect on-device:
// if storage is int64, every odd 32-bit word (high half, positions < 2^32)
// within the first SQ words is zero. If int32, word[1] = position 1 = 1 != 0.
// Only the first SQ*4 bytes are inspected, which both layouts own.
__global__ void posdetect_kernel(const unsigned int* __restrict__ p) {
    __shared__ int ok;
    if (threadIdx.x == 0) ok = 1;
    __syncthreads();
    int bad = 0;
    for (int i = threadIdx.x; i < SQ/2; i += blockDim.x)
        if (p[2*i+1] != 0u) bad = 1;
    if (bad) atomicAnd(&ok, 0);
    __syncthreads();
    if (threadIdx.x == 0) g_pos64 = ok;
}

__global__ void posconv_kernel(const void* __restrict__ p) {
    int i = blockIdx.x*blockDim.x + threadIdx.x;
    if (i >= SQ) return;
    long long v = g_pos64 ? ((const long long*)p)[i]
                          : (long long)((const int*)p)[i];
    g_posf[i] = (float)v;
}

// ------------------------- RMSNorm -------------------------
__global__ void rmsnorm_kernel(const float* __restrict__ x, const float* __restrict__ w,
                               float* __restrict__ o) {
    int row = blockIdx.x;
    const float* xr = x + (size_t)row*HDIM;
    float s = 0.f;
    for (int c = threadIdx.x; c < HDIM; c += blockDim.x) { float v = xr[c]; s += v*v; }
    __shared__ float red[8];
    for (int off = 16; off; off >>= 1) s += __shfl_xor_sync(0xffffffffu, s, off);
    int warp = threadIdx.x >> 5, lane = threadIdx.x & 31;
    if (lane == 0) red[warp] = s;
    __syncthreads();
    if (warp == 0) {
        float t = (lane < 8) ? red[lane] : 0.f;
        for (int off = 4; off; off >>= 1) t += __shfl_xor_sync(0xffffffffu, t, off);
        if (lane == 0) red[0] = t;
    }
    __syncthreads();
    float inv = rsqrtf(red[0] / (float)HDIM + 1e-5f);
    float* orow = o + (size_t)row*HDIM;
    for (int c = threadIdx.x; c < HDIM; c += blockDim.x) orow[c] = xr[c] * inv * w[c];
}

// ------------------------- GEMM (NT): C[M,N] = A[M,K] @ B[N,K]^T (+R) -------------------------
#define BM 128
#define BN 128
#define BK 16

__device__ __forceinline__ void gemm_body(
    const float* __restrict__ A, const float* __restrict__ B,
    float* __restrict__ C, const float* __restrict__ R,
    int m0, int Mend, int n0, int N, int K)
{
    __shared__ float As[BK][BM+4];
    __shared__ float Bs[BK][BN+4];
    int tid = threadIdx.x;
    int tx = tid & 15, ty = tid >> 4;
    float acc[8][8];
#pragma unroll
    for (int i = 0; i < 8; i++)
#pragma unroll
        for (int j = 0; j < 8; j++) acc[i][j] = 0.f;

    for (int ks = 0; ks < K; ks += BK) {
#pragma unroll
        for (int l = 0; l < 2; l++) {
            int idx = tid + l*256;
            int r  = idx >> 2;
            int kq = (idx & 3) << 2;
            int m = m0 + r;
            float4 va = make_float4(0.f,0.f,0.f,0.f);
            if (m < Mend) va = *(const float4*)(A + (size_t)m*K + ks + kq);
            As[kq+0][r] = va.x; As[kq+1][r] = va.y; As[kq+2][r] = va.z; As[kq+3][r] = va.w;
            int n = n0 + r;
            float4 vb = make_float4(0.f,0.f,0.f,0.f);
            if (n < N) vb = *(const float4*)(B + (size_t)n*K + ks + kq);
            Bs[kq+0][r] = vb.x; Bs[kq+1][r] = vb.y; Bs[kq+2][r] = vb.z; Bs[kq+3][r] = vb.w;
        }
        __syncthreads();
#pragma unroll
        for (int kk = 0; kk < BK; kk++) {
            float a[8], b[8];
#pragma unroll
            for (int i = 0; i < 8; i++) a[i] = As[kk][ty*8+i];
#pragma unroll
            for (int j = 0; j < 8; j++) b[j] = Bs[kk][tx*8+j];
#pragma unroll
            for (int i = 0; i < 8; i++)
#pragma unroll
                for (int j = 0; j < 8; j++) acc[i][j] += a[i]*b[j];
        }
        __syncthreads();
    }
#pragma unroll
    for (int i = 0; i < 8; i++) {
        int m = m0 + ty*8 + i;
        if (m >= Mend) continue;
#pragma unroll
        for (int j = 0; j < 8; j++) {
            int n = n0 + tx*8 + j;
            if (n >= N) continue;
            float vo = acc[i][j];
            if (R) vo += R[(size_t)m*N + n];
            C[(size_t)m*N + n] = vo;
        }
    }
}

__global__ __launch_bounds__(256) void gemm_nt_kernel(
    const float* __restrict__ A, const float* __restrict__ B,
    float* __restrict__ C, const float* __restrict__ R, int M, int N, int K) {
    gemm_body(A, B, C, R, blockIdx.y*BM, M, blockIdx.x*BN, N, K);
}

__global__ __launch_bounds__(256) void gemm_nt_group_kernel(
    const float* __restrict__ A, const float* __restrict__ Ball,
    float* __restrict__ C, int N, int K) {
    int e = blockIdx.z;
    int mstart = g_off[e], mend = g_off[e+1];
    int m0 = mstart + blockIdx.y*BM;
    if (m0 >= mend) return;
    gemm_body(A, Ball + (size_t)e*N*K, C, nullptr, m0, mend, blockIdx.x*BN, N, K);
}

// ------------------------- RoPE (in-place on q,k) -------------------------
__global__ void rope_kernel(float* __restrict__ q, float* __restrict__ k) {
    int s  = blockIdx.x;
    int hh = blockIdx.y;
    int d2 = threadIdx.x;   // 0..31
    float* p;
    if (hh < NHEAD) p = q + (size_t)s*(NHEAD*HD) + hh*HD;
    else            p = k + (size_t)s*(NKVH*HD) + (hh-NHEAD)*HD;
    float ps = g_posf[s];
    float inv = powf(10000.f, -((float)d2) / 32.f);
    float ang = ps * inv;
    float sn, cs;
    sincosf(ang, &sn, &cs);
    float x1 = p[d2], x2 = p[d2+32];
    p[d2]    = x1*cs - x2*sn;
    p[d2+32] = x2*cs + x1*sn;
}

// ------------------------- Flash attention (causal, fp32) -------------------------
#define QT 64
#define KT 32
#define APAD 68

__global__ __launch_bounds__(256) void attn_kernel(
    const float* __restrict__ q, const float* __restrict__ k,
    const float* __restrict__ v, float* __restrict__ ctx) {
    __shared__ float Qs[QT][APAD];
    __shared__ float Ks[KT][APAD];
    __shared__ float Vs[KT][APAD];
    int qt = blockIdx.x, h = blockIdx.y;
    int kvh = h >> 2;
    int tid = threadIdx.x;
    int r  = tid >> 2;      // 0..63 : query row within tile
    int cg = tid & 3;       // column group

#pragma unroll
    for (int l = 0; l < 4; l++) {
        int idx = tid + l*256;
        int rr = idx >> 4, dq = (idx & 15) << 2;
        *(float4*)&Qs[rr][dq] =
            *(const float4*)(q + (size_t)(qt*QT+rr)*(NHEAD*HD) + h*HD + dq);
    }
    __syncthreads();

    float m = -INFINITY, l = 0.f;
    float o[64];
#pragma unroll
    for (int d = 0; d < 64; d++) o[d] = 0.f;

    int jmax = 2*qt + 1;
    int qrow = qt*QT + r;
    for (int j = 0; j <= jmax; j++) {
#pragma unroll
        for (int lq = 0; lq < 2; lq++) {
            int idx = tid + lq*256;
            int rr = idx >> 4, dq = (idx & 15) << 2;
            size_t goff = (size_t)(j*KT+rr)*(NKVH*HD) + kvh*HD + dq;
            *(float4*)&Ks[rr][dq] = *(const float4*)(k + goff);
            *(float4*)&Vs[rr][dq] = *(const float4*)(v + goff);
        }
        __syncthreads();

        float s[8];
#pragma unroll
        for (int jj = 0; jj < 8; jj++) s[jj] = 0.f;
        const float4* Q4 = (const float4*)&Qs[r][0];
#pragma unroll 4
        for (int d4 = 0; d4 < 16; d4++) {
            float4 q4 = Q4[d4];
#pragma unroll
            for (int jj = 0; jj < 8; jj++) {
                int c = cg + 4*jj;
                float4 k4 = *(const float4*)&Ks[c][d4 << 2];
                s[jj] += q4.x*k4.x + q4.y*k4.y + q4.z*k4.z + q4.w*k4.w;
            }
        }
        float mloc = -INFINITY;
#pragma unroll
        for (int jj = 0; jj < 8; jj++) {
            s[jj] *= 0.125f;                    // 1/sqrt(64)
            int kk = j*KT + cg + 4*jj;
            if (kk > qrow) s[jj] = -1e30f;
            mloc = fmaxf(mloc, s[jj]);
        }
        mloc = fmaxf(mloc, __shfl_xor_sync(0xffffffffu, mloc, 1));
        mloc = fmaxf(mloc, __shfl_xor_sync(0xffffffffu, mloc, 2));
        float mnew = fmaxf(m, mloc);
        float scale = __expf(m - mnew);
        float p[8]; float psum = 0.f;
#pragma unroll
        for (int jj = 0; jj < 8; jj++) { p[jj] = __expf(s[jj] - mnew); psum += p[jj]; }
        psum += __shfl_xor_sync(0xffffffffu, psum, 1);
        psum += __shfl_xor_sync(0xffffffffu, psum, 2);
        l = l*scale + psum;
        m = mnew;
#pragma unroll
        for (int d = 0; d < 64; d++) o[d] *= scale;
#pragma unroll
        for (int jj = 0; jj < 8; jj++) {
            int c = cg + 4*jj;
            float pj = p[jj];
            const float4* V4 = (const float4*)&Vs[c][0];
#pragma unroll
            for (int d4 = 0; d4 < 16; d4++) {
                float4 v4 = V4[d4];
                o[d4*4+0] += pj*v4.x; o[d4*4+1] += pj*v4.y;
                o[d4*4+2] += pj*v4.z; o[d4*4+3] += pj*v4.w;
            }
        }
        __syncthreads();
    }
#pragma unroll
    for (int d = 0; d < 64; d++) {
        o[d] += __shfl_xor_sync(0xffffffffu, o[d], 1);
        o[d] += __shfl_xor_sync(0xffffffffu, o[d], 2);
    }
    float invl = 1.f / l;
    size_t base = (size_t)qrow*(NHEAD*HD) + h*HD;
    for (int d = cg*16; d < cg*16 + 16; d++) ctx[base + d] = o[d] * invl;
}

// ------------------------- MoE routing -------------------------
__global__ void reset_kernel() {
    int i = threadIdx.x;
    if (i < NE) { g_cnt[i] = 0; g_cur[i] = 0; }
}

__global__ void router_kernel(const float* __restrict__ x, const float* __restrict__ wg) {
    int t = blockIdx.x;
    int warp = threadIdx.x >> 5, lane = threadIdx.x & 31;
    const float* xr = x + (size_t)t*HDIM;
    const float* wr = wg + (size_t)warp*HDIM;
    float s = 0.f;
    for (int c = lane; c < HDIM; c += 32) s += xr[c]*wr[c];
    for (int off = 16; off; off >>= 1) s += __shfl_xor_sync(0xffffffffu, s, off);
    __shared__ float lg[NE];
    if (lane == 0) lg[warp] = s;
    __syncthreads();
    if (threadIdx.x == 0) {
        int i0 = 0;
        for (int e = 1; e < NE; e++) if (lg[e] > lg[i0]) i0 = e;
        int i1 = (i0 == 0) ? 1 : 0;
        for (int e = 0; e < NE; e++) { if (e == i0) continue; if (lg[e] > lg[i1]) i1 = e; }
        float w0 = 1.f / (1.f + __expf(lg[i1] - lg[i0]));
        for (int e = 0; e < NE; e++) g_rlog[t*NE + e] = lg[e];
        g_tok2e[t*2]   = i0; g_tok2e[t*2+1] = i1;
        g_tok2w[t*2]   = w0; g_tok2w[t*2+1] = 1.f - w0;
        atomicAdd(&g_cnt[i0], 1);
        atomicAdd(&g_cnt[i1], 1);
    }
}

__global__ void scan_kernel() {
    if (threadIdx.x == 0) {
        int acc = 0;
        for (int e = 0; e < NE; e++) { g_off[e] = acc; acc += g_cnt[e]; }
        g_off[NE] = acc;
    }
}

__global__ void scatter_kernel() {
    int t = blockIdx.x*blockDim.x + threadIdx.x;
    if (t >= SQ) return;
#pragma unroll
    for (int sl = 0; sl < 2; sl++) {
        int e = g_tok2e[t*2+sl];
        int rrel = atomicAdd(&g_cur[e], 1);
        int rr = g_off[e] + rrel;
        g_rows[rr] = t;
        g_tok2row[t*2+sl] = rr;
    }
}

__global__ void gather_kernel() {
    int total = SQ*2*(HDIM/4);
    for (int idx = blockIdx.x*blockDim.x + threadIdx.x; idx < total; idx += gridDim.x*blockDim.x) {
        int row = idx / (HDIM/4);
        int c4  = idx % (HDIM/4);
        ((float4*)g_xg)[(size_t)row*(HDIM/4) + c4] =
            ((const float4*)g_xn2)[(size_t)g_rows[row]*(HDIM/4) + c4];
    }
}

__global__ void silu_kernel() {
    size_t total = (size_t)SQ*2*IDIM;
    for (size_t i = blockIdx.x*(size_t)blockDim.x + threadIdx.x; i < total;
         i += (size_t)gridDim.x*blockDim.x) {
        float x = g_b1[i];
        float g = x / (1.f + __expf(-x));
        g_b1[i] = g * g_b3[i];
    }
}

__global__ void finalize_kernel(const float* __restrict__ resid, float* __restrict__ out) {
    int t = blockIdx.x;
    int r0 = g_tok2row[t*2], r1 = g_tok2row[t*2+1];
    float w0 = g_tok2w[t*2], w1 = g_tok2w[t*2+1];
    for (int c = threadIdx.x; c < HDIM; c += blockDim.x) {
        out[(size_t)t*HDIM + c] = resid[(size_t)t*HDIM + c]
            + w0*g_y[(size_t)r0*HDIM + c] + w1*g_y[(size_t)r1*HDIM + c];
    }
}

// ------------------------- output tail writers -------------------------
// gate_logits output = input gate_logits with layer 0 replaced by router logits
__global__ void gate_kernel(float* __restrict__ dst, const float* __restrict__ gin) {
    int i = blockIdx.x*blockDim.x + threadIdx.x;
    int total = 4*SQ*NE;
    if (i < total) dst[i] = (i < SQ*NE) ? g_rlog[i] : gin[i];
}

__global__ void posf_kernel(float* __restrict__ dst, int n) {
    int i = blockIdx.x*blockDim.x + threadIdx.x;
    if (i < n) dst[i] = g_posf[i];
}

__global__ void posraw_kernel(float* __restrict__ dst, int n) {
    int i = blockIdx.x*blockDim.x + threadIdx.x;
    if (i < n) ((long long*)dst)[i] = (long long)g_posf[i];
}

__global__ void zerofill_kernel(float* __restrict__ dst, int n) {
    int i = blockIdx.x*blockDim.x + threadIdx.x;
    if (i < n) dst[i] = 0.f;
}

// ------------------------- launch -------------------------
extern "C" void kernel_launch(void* const* d_in, const int* in_sizes, int n_in,
                              void* d_out, int out_size) {
    const float* hidden = (const float*)d_in[0];
    const void*  posraw = d_in[1];
    const float* gatein = (const float*)d_in[2];
    const float* ln1 = (const float*)d_in[3];
    const float* ln2 = (const float*)d_in[4];
    const float* wq  = (const float*)d_in[5];
    const float* wk  = (const float*)d_in[6];
    const float* wv  = (const float*)d_in[7];
    const float* wo  = (const float*)d_in[8];
    const float* wg  = (const float*)d_in[9];
    const float* w1  = (const float*)d_in[10];
    const float* w2  = (const float*)d_in[11];
    const float* w3  = (const float*)d_in[12];

    float *xn1,*q,*k,*v,*ctx,*resid1,*xn2,*xg,*b1,*b3,*y;
    cudaGetSymbolAddress((void**)&xn1,    g_xn1);
    cudaGetSymbolAddress((void**)&q,      g_q);
    cudaGetSymbolAddress((void**)&k,      g_k);
    cudaGetSymbolAddress((void**)&v,      g_v);
    cudaGetSymbolAddress((void**)&ctx,    g_ctx);
    cudaGetSymbolAddress((void**)&resid1, g_resid1);
    cudaGetSymbolAddress((void**)&xn2,    g_xn2);
    cudaGetSymbolAddress((void**)&xg,     g_xg);
    cudaGetSymbolAddress((void**)&b1,     g_b1);
    cudaGetSymbolAddress((void**)&b3,     g_b3);
    cudaGetSymbolAddress((void**)&y,      g_y);

    // position normalization (int32 vs int64 storage)
    posdetect_kernel<<<1, 256>>>((const unsigned int*)posraw);
    posconv_kernel<<<SQ/256, 256>>>(posraw);

    // attention path
    rmsnorm_kernel<<<SQ, 256>>>(hidden, ln1, xn1);
    dim3 gq(HDIM/BN, SQ/BM);
    dim3 gkv((NKVH*HD)/BN, SQ/BM);
    gemm_nt_kernel<<<gq,  256>>>(xn1, wq, q, nullptr, SQ, NHEAD*HD, HDIM);
    gemm_nt_kernel<<<gkv, 256>>>(xn1, wk, k, nullptr, SQ, NKVH*HD, HDIM);
    gemm_nt_kernel<<<gkv, 256>>>(xn1, wv, v, nullptr, SQ, NKVH*HD, HDIM);
    rope_kernel<<<dim3(SQ, NHEAD+NKVH), 32>>>(q, k);
    attn_kernel<<<dim3(SQ/QT, NHEAD), 256>>>(q, k, v, ctx);
    gemm_nt_kernel<<<gq, 256>>>(ctx, wo, resid1, hidden, SQ, HDIM, HDIM);  // + residual

    // MoE path
    rmsnorm_kernel<<<SQ, 256>>>(resid1, ln2, xn2);
    reset_kernel<<<1, 32>>>();
    router_kernel<<<SQ, 256>>>(xn2, wg);
    scan_kernel<<<1, 32>>>();
    scatter_kernel<<<SQ/256, 256>>>();
    gather_kernel<<<512, 256>>>();
    gemm_nt_group_kernel<<<dim3(IDIM/BN, SQ/BM, NE), 256>>>(xg, w1, b1, IDIM, HDIM);
    gemm_nt_group_kernel<<<dim3(IDIM/BN, SQ/BM, NE), 256>>>(xg, w3, b3, IDIM, HDIM);
    silu_kernel<<<2048, 256>>>();
    gemm_nt_group_kernel<<<dim3(HDIM/BN, SQ/BM, NE), 256>>>(b1, w2, y, HDIM, IDIM);

    float* out = (float*)d_out;
    const int HTOT = SQ*HDIM;
    const int GTOT = 4*SQ*NE;
    finalize_kernel<<<SQ, 256>>>(resid1, out);

    int rem = out_size - HTOT;
    if (rem >= GTOT) {
        gate_kernel<<<(GTOT+255)/256, 256>>>(out + (out_size - GTOT), gatein);
        rem -= GTOT;
    }
    if (rem == SQ) {
        posf_kernel<<<(SQ+255)/256, 256>>>(out + HTOT, SQ);
    } else if (rem == 2*SQ) {
        posraw_kernel<<<(SQ+255)/256, 256>>>(out + HTOT, SQ);
    } else if (rem > 0) {
        zerofill_kernel<<<(rem+255)/256, 256>>>(out + HTOT, rem);
    }
}

// round 3
// speedup vs baseline: 1.8784x; 1.8784x over previous
#include <cuda_runtime.h>
#include <math.h>

#define HDIM 2048
#define SQ   2048
#define NHEAD 32
#define NKVH  8
#define HD    64
#define IDIM  4096
#define NE    8

// ------------------------- scratch (static, no allocs) -------------------------
__device__ float g_xn1[SQ*HDIM];
__device__ float g_q[SQ*NHEAD*HD];
__device__ float g_k[SQ*NKVH*HD];
__device__ float g_v[SQ*NKVH*HD];
__device__ float g_ctx[SQ*NHEAD*HD];
__device__ float g_resid1[SQ*HDIM];
__device__ float g_xn2[SQ*HDIM];
__device__ float g_rlog[SQ*NE];
__device__ int   g_tok2e[SQ*2];
__device__ float g_tok2w[SQ*2];
__device__ int   g_tok2row[SQ*2];
__device__ int   g_rows[SQ*2];
__device__ int   g_cnt[NE];
__device__ int   g_off[NE+1];
__device__ int   g_cur[NE];
__device__ float g_xg[SQ*2*HDIM];
__device__ float g_b1[SQ*2*IDIM];
__device__ float g_b3[SQ*2*IDIM];
__device__ float g_y[SQ*2*HDIM];
__device__ int   g_pos64;
__device__ float g_posf[SQ];

// ------------------------- position width detection -------------------------
__global__ void posdetect_kernel(const unsigned int* __restrict__ p) {
    __shared__ int ok;
    if (threadIdx.x == 0) ok = 1;
    __syncthreads();
    int bad = 0;
    for (int i = threadIdx.x; i < SQ/2; i += blockDim.x)
        if (p[2*i+1] != 0u) bad = 1;
    if (bad) atomicAnd(&ok, 0);
    __syncthreads();
    if (threadIdx.x == 0) g_pos64 = ok;
}

__global__ void posconv_kernel(const void* __restrict__ p) {
    int i = blockIdx.x*blockDim.x + threadIdx.x;
    if (i >= SQ) return;
    long long v = g_pos64 ? ((const long long*)p)[i]
                          : (long long)((const int*)p)[i];
    g_posf[i] = (float)v;
}

// ------------------------- RMSNorm -------------------------
__global__ void rmsnorm_kernel(const float* __restrict__ x, const float* __restrict__ w,
                               float* __restrict__ o) {
    int row = blockIdx.x;
    const float* xr = x + (size_t)row*HDIM;
    float s = 0.f;
    for (int c = threadIdx.x; c < HDIM; c += blockDim.x) { float v = xr[c]; s += v*v; }
    __shared__ float red[8];
    for (int off = 16; off; off >>= 1) s += __shfl_xor_sync(0xffffffffu, s, off);
    int warp = threadIdx.x >> 5, lane = threadIdx.x & 31;
    if (lane == 0) red[warp] = s;
    __syncthreads();
    if (warp == 0) {
        float t = (lane < 8) ? red[lane] : 0.f;
        for (int off = 4; off; off >>= 1) t += __shfl_xor_sync(0xffffffffu, t, off);
        if (lane == 0) red[0] = t;
    }
    __syncthreads();
    float inv = rsqrtf(red[0] / (float)HDIM + 1e-5f);
    float* orow = o + (size_t)row*HDIM;
    for (int c = threadIdx.x; c < HDIM; c += blockDim.x) orow[c] = xr[c] * inv * w[c];
}

// ------------------------- TF32 tensor-core GEMM (NT) -------------------------
// C[M,N] = A[M,K] @ B[N,K]^T (+R), fp32 in/out, tf32 MMA.
#define BM 128
#define BN 128
#define BK 32
#define LDSW 40   // row stride in floats (32 + 8 pad -> conflict-free LDS.64)

__device__ __forceinline__ float f2tf32(float f) {
    unsigned r;
    asm("cvt.rna.tf32.f32 %0, %1;" : "=r"(r) : "f"(f));
    return __uint_as_float(r);
}

__device__ __forceinline__ void mma_tf32(float c[4], float2 alo, float2 ahi, float2 b) {
    asm volatile(
        "mma.sync.aligned.m16n8k8.row.col.f32.tf32.tf32.f32 "
        "{%0,%1,%2,%3}, {%4,%5,%6,%7}, {%8,%9}, {%0,%1,%2,%3};\n"
        : "+f"(c[0]), "+f"(c[1]), "+f"(c[2]), "+f"(c[3])
        : "r"(__float_as_uint(alo.x)), "r"(__float_as_uint(ahi.x)),
          "r"(__float_as_uint(alo.y)), "r"(__float_as_uint(ahi.y)),
          "r"(__float_as_uint(b.x)),   "r"(__float_as_uint(b.y)));
}

__device__ __forceinline__ void gemm_tf32_body(
    const float* __restrict__ A, const float* __restrict__ B,
    float* __restrict__ C, const float* __restrict__ R,
    int m0, int Mend, int n0, int N, int K)
{
    __shared__ float As[BM*LDSW];
    __shared__ float Bs[BN*LDSW];
    int tid = threadIdx.x;
    int lane = tid & 31, wid = tid >> 5;
    int wm = (wid & 1) * 64;       // 2 warps over M
    int wn = (wid >> 1) * 32;      // 4 warps over N
    int tig = lane & 3, grp = lane >> 2;

    float acc[4][4][4];
#pragma unroll
    for (int i = 0; i < 4; i++)
#pragma unroll
        for (int j = 0; j < 4; j++)
#pragma unroll
            for (int r = 0; r < 4; r++) acc[i][j][r] = 0.f;

    for (int ks = 0; ks < K; ks += BK) {
        // global -> smem, tf32-rounded, interleaved (k, k+4) pairing:
        // float col for element k: (k/8)*8 + (k%4)*2 + (k%8)/4
#pragma unroll
        for (int l = 0; l < 4; l++) {
            int fid = tid + l*256;
            int row = fid >> 3;
            int c4  = fid & 7;          // which float4 along K
            int k   = c4 << 2;
            int colbase = (c4 >> 1)*8 + (c4 & 1);
            int m = m0 + row;
            float4 va = make_float4(0.f,0.f,0.f,0.f);
            if (m < Mend) va = *(const float4*)(A + (size_t)m*K + ks + k);
            float* ad = &As[row*LDSW + colbase];
            ad[0] = f2tf32(va.x); ad[2] = f2tf32(va.y);
            ad[4] = f2tf32(va.z); ad[6] = f2tf32(va.w);
            int n = n0 + row;
            float4 vb = make_float4(0.f,0.f,0.f,0.f);
            if (n < N) vb = *(const float4*)(B + (size_t)n*K + ks + k);
            float* bd = &Bs[row*LDSW + colbase];
            bd[0] = f2tf32(vb.x); bd[2] = f2tf32(vb.y);
            bd[4] = f2tf32(vb.z); bd[6] = f2tf32(vb.w);
        }
        __syncthreads();
#pragma unroll
        for (int s = 0; s < 4; s++) {
            float2 alo[4], ahi[4], bfr[4];
#pragma unroll
            for (int i = 0; i < 4; i++) {
                int r0 = wm + i*16 + grp;
                alo[i] = *(const float2*)&As[r0*LDSW + s*8 + tig*2];
                ahi[i] = *(const float2*)&As[(r0+8)*LDSW + s*8 + tig*2];
            }
#pragma unroll
            for (int j = 0; j < 4; j++) {
                int n = wn + j*8 + grp;
                bfr[j] = *(const float2*)&Bs[n*LDSW + s*8 + tig*2];
            }
#pragma unroll
            for (int i = 0; i < 4; i++)
#pragma unroll
                for (int j = 0; j < 4; j++)
                    mma_tf32(acc[i][j], alo[i], ahi[i], bfr[j]);
        }
        __syncthreads();
    }

    // epilogue
#pragma unroll
    for (int i = 0; i < 4; i++) {
#pragma unroll
        for (int j = 0; j < 4; j++) {
            int row = m0 + wm + i*16 + grp;
            int col = n0 + wn + j*8 + tig*2;
            if (col + 1 < N || col < N) {
                if (row < Mend) {
                    float2 v = make_float2(acc[i][j][0], acc[i][j][1]);
                    if (R) { v.x += R[(size_t)row*N + col]; v.y += R[(size_t)row*N + col+1]; }
                    *(float2*)(C + (size_t)row*N + col) = v;
                }
                if (row + 8 < Mend) {
                    float2 v = make_float2(acc[i][j][2], acc[i][j][3]);
                    if (R) { v.x += R[(size_t)(row+8)*N + col]; v.y += R[(size_t)(row+8)*N + col+1]; }
                    *(float2*)(C + (size_t)(row+8)*N + col) = v;
                }
            }
        }
    }
}

__global__ __launch_bounds__(256, 2) void gemm_tf32_kernel(
    const float* __restrict__ A, const float* __restrict__ B,
    float* __restrict__ C, const float* __restrict__ R, int M, int N, int K) {
    gemm_tf32_body(A, B, C, R, blockIdx.y*BM, M, blockIdx.x*BN, N, K);
}

__global__ __launch_bounds__(256, 2) void gemm_tf32_group_kernel(
    const float* __restrict__ A, const float* __restrict__ Ball,
    float* __restrict__ C, int N, int K) {
    int e = blockIdx.z;
    int mstart = g_off[e], mend = g_off[e+1];
    int m0 = mstart + blockIdx.y*BM;
    if (m0 >= mend) return;
    gemm_tf32_body(A, Ball + (size_t)e*N*K, C, nullptr, m0, mend, blockIdx.x*BN, N, K);
}

// ------------------------- RoPE (in-place on q,k) -------------------------
__global__ void rope_kernel(float* __restrict__ q, float* __restrict__ k) {
    int s  = blockIdx.x;
    int hh = blockIdx.y;
    int d2 = threadIdx.x;   // 0..31
    float* p;
    if (hh < NHEAD) p = q + (size_t)s*(NHEAD*HD) + hh*HD;
    else            p = k + (size_t)s*(NKVH*HD) + (hh-NHEAD)*HD;
    float ps = g_posf[s];
    float inv = powf(10000.f, -((float)d2) / 32.f);
    float ang = ps * inv;
    float sn, cs;
    sincosf(ang, &sn, &cs);
    float x1 = p[d2], x2 = p[d2+32];
    p[d2]    = x1*cs - x2*sn;
    p[d2+32] = x2*cs + x1*sn;
}

// ------------------------- Flash attention (causal, fp32) -------------------------
#define QT 64
#define KT 32
#define APAD 68

__global__ __launch_bounds__(256) void attn_kernel(
    const float* __restrict__ q, const float* __restrict__ k,
    const float* __restrict__ v, float* __restrict__ ctx) {
    __shared__ float Qs[QT][APAD];
    __shared__ float Ks[KT][APAD];
    __shared__ float Vs[KT][APAD];
    int qt = blockIdx.x, h = blockIdx.y;
    int kvh = h >> 2;
    int tid = threadIdx.x;
    int r  = tid >> 2;
    int cg = tid & 3;

#pragma unroll
    for (int l = 0; l < 4; l++) {
        int idx = tid + l*256;
        int rr = idx >> 4, dq = (idx & 15) << 2;
        *(float4*)&Qs[rr][dq] =
            *(const float4*)(q + (size_t)(qt*QT+rr)*(NHEAD*HD) + h*HD + dq);
    }
    __syncthreads();

    float m = -INFINITY, l = 0.f;
    float o[64];
#pragma unroll
    for (int d = 0; d < 64; d++) o[d] = 0.f;

    int jmax = 2*qt + 1;
    int qrow = qt*QT + r;
    for (int j = 0; j <= jmax; j++) {
#pragma unroll
        for (int lq = 0; lq < 2; lq++) {
            int idx = tid + lq*256;
            int rr = idx >> 4, dq = (idx & 15) << 2;
            size_t goff = (size_t)(j*KT+rr)*(NKVH*HD) + kvh*HD + dq;
            *(float4*)&Ks[rr][dq] = *(const float4*)(k + goff);
            *(float4*)&Vs[rr][dq] = *(const float4*)(v + goff);
        }
        __syncthreads();

        float s[8];
#pragma unroll
        for (int jj = 0; jj < 8; jj++) s[jj] = 0.f;
        const float4* Q4 = (const float4*)&Qs[r][0];
#pragma unroll 4
        for (int d4 = 0; d4 < 16; d4++) {
            float4 q4 = Q4[d4];
#pragma unroll
            for (int jj = 0; jj < 8; jj++) {
                int c = cg + 4*jj;
                float4 k4 = *(const float4*)&Ks[c][d4 << 2];
                s[jj] += q4.x*k4.x + q4.y*k4.y + q4.z*k4.z + q4.w*k4.w;
            }
        }
        float mloc = -INFINITY;
#pragma unroll
        for (int jj = 0; jj < 8; jj++) {
            s[jj] *= 0.125f;
            int kk = j*KT + cg + 4*jj;
            if (kk > qrow) s[jj] = -1e30f;
            mloc = fmaxf(mloc, s[jj]);
        }
        mloc = fmaxf(mloc, __shfl_xor_sync(0xffffffffu, mloc, 1));
        mloc = fmaxf(mloc, __shfl_xor_sync(0xffffffffu, mloc, 2));
        float mnew = fmaxf(m, mloc);
        float scale = __expf(m - mnew);
        float p[8]; float psum = 0.f;
#pragma unroll
        for (int jj = 0; jj < 8; jj++) { p[jj] = __expf(s[jj] - mnew); psum += p[jj]; }
        psum += __shfl_xor_sync(0xffffffffu, psum, 1);
        psum += __shfl_xor_sync(0xffffffffu, psum, 2);
        l = l*scale + psum;
        m = mnew;
#pragma unroll
        for (int d = 0; d < 64; d++) o[d] *= scale;
#pragma unroll
        for (int jj = 0; jj < 8; jj++) {
            int c = cg + 4*jj;
            float pj = p[jj];
            const float4* V4 = (const float4*)&Vs[c][0];
#pragma unroll
            for (int d4 = 0; d4 < 16; d4++) {
                float4 v4 = V4[d4];
                o[d4*4+0] += pj*v4.x; o[d4*4+1] += pj*v4.y;
                o[d4*4+2] += pj*v4.z; o[d4*4+3] += pj*v4.w;
            }
        }
        __syncthreads();
    }
#pragma unroll
    for (int d = 0; d < 64; d++) {
        o[d] += __shfl_xor_sync(0xffffffffu, o[d], 1);
        o[d] += __shfl_xor_sync(0xffffffffu, o[d], 2);
    }
    float invl = 1.f / l;
    size_t base = (size_t)qrow*(NHEAD*HD) + h*HD;
    for (int d = cg*16; d < cg*16 + 16; d++) ctx[base + d] = o[d] * invl;
}

// ------------------------- MoE routing -------------------------
__global__ void reset_kernel() {
    int i = threadIdx.x;
    if (i < NE) { g_cnt[i] = 0; g_cur[i] = 0; }
}

__global__ void router_kernel(const float* __restrict__ x, const float* __restrict__ wg) {
    int t = blockIdx.x;
    int warp = threadIdx.x >> 5, lane = threadIdx.x & 31;
    const float* xr = x + (size_t)t*HDIM;
    const float* wr = wg + (size_t)warp*HDIM;
    float s = 0.f;
    for (int c = lane; c < HDIM; c += 32) s += xr[c]*wr[c];
    for (int off = 16; off; off >>= 1) s += __shfl_xor_sync(0xffffffffu, s, off);
    __shared__ float lg[NE];
    if (lane == 0) lg[warp] = s;
    __syncthreads();
    if (threadIdx.x == 0) {
        int i0 = 0;
        for (int e = 1; e < NE; e++) if (lg[e] > lg[i0]) i0 = e;
        int i1 = (i0 == 0) ? 1 : 0;
        for (int e = 0; e < NE; e++) { if (e == i0) continue; if (lg[e] > lg[i1]) i1 = e; }
        float w0 = 1.f / (1.f + __expf(lg[i1] - lg[i0]));
        for (int e = 0; e < NE; e++) g_rlog[t*NE + e] = lg[e];
        g_tok2e[t*2]   = i0; g_tok2e[t*2+1] = i1;
        g_tok2w[t*2]   = w0; g_tok2w[t*2+1] = 1.f - w0;
        atomicAdd(&g_cnt[i0], 1);
        atomicAdd(&g_cnt[i1], 1);
    }
}

__global__ void scan_kernel() {
    if (threadIdx.x == 0) {
        int acc = 0;
        for (int e = 0; e < NE; e++) { g_off[e] = acc; acc += g_cnt[e]; }
        g_off[NE] = acc;
    }
}

__global__ void scatter_kernel() {
    int t = blockIdx.x*blockDim.x + threadIdx.x;
    if (t >= SQ) return;
#pragma unroll
    for (int sl = 0; sl < 2; sl++) {
        int e = g_tok2e[t*2+sl];
        int rrel = atomicAdd(&g_cur[e], 1);
        int rr = g_off[e] + rrel;
        g_rows[rr] = t;
        g_tok2row[t*2+sl] = rr;
    }
}

__global__ void gather_kernel() {
    int total = SQ*2*(HDIM/4);
    for (int idx = blockIdx.x*blockDim.x + threadIdx.x; idx < total; idx += gridDim.x*blockDim.x) {
        int row = idx / (HDIM/4);
        int c4  = idx % (HDIM/4);
        ((float4*)g_xg)[(size_t)row*(HDIM/4) + c4] =
            ((const float4*)g_xn2)[(size_t)g_rows[row]*(HDIM/4) + c4];
    }
}

__global__ void silu_kernel() {
    size_t total = (size_t)SQ*2*IDIM;
    for (size_t i = blockIdx.x*(size_t)blockDim.x + threadIdx.x; i < total;
         i += (size_t)gridDim.x*blockDim.x) {
        float x = g_b1[i];
        float g = x / (1.f + __expf(-x));
        g_b1[i] = g * g_b3[i];
    }
}

__global__ void finalize_kernel(const float* __restrict__ resid, float* __restrict__ out) {
    int t = blockIdx.x;
    int r0 = g_tok2row[t*2], r1 = g_tok2row[t*2+1];
    float w0 = g_tok2w[t*2], w1 = g_tok2w[t*2+1];
    for (int c = threadIdx.x; c < HDIM; c += blockDim.x) {
        out[(size_t)t*HDIM + c] = resid[(size_t)t*HDIM + c]
            + w0*g_y[(size_t)r0*HDIM + c] + w1*g_y[(size_t)r1*HDIM + c];
    }
}

// ------------------------- output tail writers -------------------------
__global__ void gate_kernel(float* __restrict__ dst, const float* __restrict__ gin) {
    int i = blockIdx.x*blockDim.x + threadIdx.x;
    int total = 4*SQ*NE;
    if (i < total) dst[i] = (i < SQ*NE) ? g_rlog[i] : gin[i];
}

__global__ void posf_kernel(float* __restrict__ dst, int n) {
    int i = blockIdx.x*blockDim.x + threadIdx.x;
    if (i < n) dst[i] = g_posf[i];
}

__global__ void posraw_kernel(float* __restrict__ dst, int n) {
    int i = blockIdx.x*blockDim.x + threadIdx.x;
    if (i < n) ((long long*)dst)[i] = (long long)g_posf[i];
}

__global__ void zerofill_kernel(float* __restrict__ dst, int n) {
    int i = blockIdx.x*blockDim.x + threadIdx.x;
    if (i < n) dst[i] = 0.f;
}

// ------------------------- launch -------------------------
extern "C" void kernel_launch(void* const* d_in, const int* in_sizes, int n_in,
                              void* d_out, int out_size) {
    const float* hidden = (const float*)d_in[0];
    const void*  posraw = d_in[1];
    const float* gatein = (const float*)d_in[2];
    const float* ln1 = (const float*)d_in[3];
    const float* ln2 = (const float*)d_in[4];
    const float* wq  = (const float*)d_in[5];
    const float* wk  = (const float*)d_in[6];
    const float* wv  = (const float*)d_in[7];
    const float* wo  = (const float*)d_in[8];
    const float* wg  = (const float*)d_in[9];
    const float* w1  = (const float*)d_in[10];
    const float* w2  = (const float*)d_in[11];
    const float* w3  = (const float*)d_in[12];

    float *xn1,*q,*k,*v,*ctx,*resid1,*xn2,*xg,*b1,*b3,*y;
    cudaGetSymbolAddress((void**)&xn1,    g_xn1);
    cudaGetSymbolAddress((void**)&q,      g_q);
    cudaGetSymbolAddress((void**)&k,      g_k);
    cudaGetSymbolAddress((void**)&v,      g_v);
    cudaGetSymbolAddress((void**)&ctx,    g_ctx);
    cudaGetSymbolAddress((void**)&resid1, g_resid1);
    cudaGetSymbolAddress((void**)&xn2,    g_xn2);
    cudaGetSymbolAddress((void**)&xg,     g_xg);
    cudaGetSymbolAddress((void**)&b1,     g_b1);
    cudaGetSymbolAddress((void**)&b3,     g_b3);
    cudaGetSymbolAddress((void**)&y,      g_y);

    posdetect_kernel<<<1, 256>>>((const unsigned int*)posraw);
    posconv_kernel<<<SQ/256, 256>>>(posraw);

    // attention path
    rmsnorm_kernel<<<SQ, 256>>>(hidden, ln1, xn1);
    dim3 gq(HDIM/BN, SQ/BM);
    dim3 gkv((NKVH*HD)/BN, SQ/BM);
    gemm_tf32_kernel<<<gq,  256>>>(xn1, wq, q, nullptr, SQ, NHEAD*HD, HDIM);
    gemm_tf32_kernel<<<gkv, 256>>>(xn1, wk, k, nullptr, SQ, NKVH*HD, HDIM);
    gemm_tf32_kernel<<<gkv, 256>>>(xn1, wv, v, nullptr, SQ, NKVH*HD, HDIM);
    rope_kernel<<<dim3(SQ, NHEAD+NKVH), 32>>>(q, k);
    attn_kernel<<<dim3(SQ/QT, NHEAD), 256>>>(q, k, v, ctx);
    gemm_tf32_kernel<<<gq, 256>>>(ctx, wo, resid1, hidden, SQ, HDIM, HDIM);

    // MoE path
    rmsnorm_kernel<<<SQ, 256>>>(resid1, ln2, xn2);
    reset_kernel<<<1, 32>>>();
    router_kernel<<<SQ, 256>>>(xn2, wg);
    scan_kernel<<<1, 32>>>();
    scatter_kernel<<<SQ/256, 256>>>();
    gather_kernel<<<512, 256>>>();
    gemm_tf32_group_kernel<<<dim3(IDIM/BN, SQ/BM, NE), 256>>>(xg, w1, b1, IDIM, HDIM);
    gemm_tf32_group_kernel<<<dim3(IDIM/BN, SQ/BM, NE), 256>>>(xg, w3, b3, IDIM, HDIM);
    silu_kernel<<<2048, 256>>>();
    gemm_tf32_group_kernel<<<dim3(HDIM/BN, SQ/BM, NE), 256>>>(b1, w2, y, HDIM, IDIM);

    float* out = (float*)d_out;
    const int HTOT = SQ*HDIM;
    const int GTOT = 4*SQ*NE;
    finalize_kernel<<<SQ, 256>>>(resid1, out);

    int rem = out_size - HTOT;
    if (rem >= GTOT) {
        gate_kernel<<<(GTOT+255)/256, 256>>>(out + (out_size - GTOT), gatein);
        rem -= GTOT;
    }
    if (rem == SQ) {
        posf_kernel<<<(SQ+255)/256, 256>>>(out + HTOT, SQ);
    } else if (rem == 2*SQ) {
        posraw_kernel<<<(SQ+255)/256, 256>>>(out + HTOT, SQ);
    } else if (rem > 0) {
        zerofill_kernel<<<(rem+255)/256, 256>>>(out + HTOT, rem);
    }
}

// round 4
// speedup vs baseline: 2.0804x; 1.1076x over previous
#include <cuda_runtime.h>
#include <math.h>

#define HDIM 2048
#define SQ   2048
#define NHEAD 32
#define NKVH  8
#define HD    64
#define IDIM  4096
#define NE    8

// ------------------------- scratch (static, no allocs) -------------------------
__device__ float g_xn1[SQ*HDIM];
__device__ float g_q[SQ*NHEAD*HD];
__device__ float g_k[SQ*NKVH*HD];
__device__ float g_v[SQ*NKVH*HD];
__device__ float g_ctx[SQ*NHEAD*HD];
__device__ float g_resid1[SQ*HDIM];
__device__ float g_xn2[SQ*HDIM];
__device__ float g_rlog[SQ*NE];
__device__ int   g_tok2e[SQ*2];
__device__ float g_tok2w[SQ*2];
__device__ int   g_tok2row[SQ*2];
__device__ int   g_rows[SQ*2];
__device__ int   g_cnt[NE];
__device__ int   g_off[NE+1];
__device__ int   g_cur[NE];
__device__ float g_xg[SQ*2*HDIM];
__device__ float g_b1[SQ*2*IDIM];
__device__ float g_b3[SQ*2*IDIM];
__device__ float g_y[SQ*2*HDIM];
__device__ int   g_pos64;
__device__ float g_posf[SQ];

// ------------------------- position width detection -------------------------
__global__ void posdetect_kernel(const unsigned int* __restrict__ p) {
    __shared__ int ok;
    if (threadIdx.x == 0) ok = 1;
    __syncthreads();
    int bad = 0;
    for (int i = threadIdx.x; i < SQ/2; i += blockDim.x)
        if (p[2*i+1] != 0u) bad = 1;
    if (bad) atomicAnd(&ok, 0);
    __syncthreads();
    if (threadIdx.x == 0) g_pos64 = ok;
}

__global__ void posconv_kernel(const void* __restrict__ p) {
    int i = blockIdx.x*blockDim.x + threadIdx.x;
    if (i >= SQ) return;
    long long v = g_pos64 ? ((const long long*)p)[i]
                          : (long long)((const int*)p)[i];
    g_posf[i] = (float)v;
}

// ------------------------- RMSNorm -------------------------
__global__ void rmsnorm_kernel(const float* __restrict__ x, const float* __restrict__ w,
                               float* __restrict__ o) {
    int row = blockIdx.x;
    const float* xr = x + (size_t)row*HDIM;
    float s = 0.f;
    for (int c = threadIdx.x; c < HDIM; c += blockDim.x) { float v = xr[c]; s += v*v; }
    __shared__ float red[8];
    for (int off = 16; off; off >>= 1) s += __shfl_xor_sync(0xffffffffu, s, off);
    int warp = threadIdx.x >> 5, lane = threadIdx.x & 31;
    if (lane == 0) red[warp] = s;
    __syncthreads();
    if (warp == 0) {
        float t = (lane < 8) ? red[lane] : 0.f;
        for (int off = 4; off; off >>= 1) t += __shfl_xor_sync(0xffffffffu, t, off);
        if (lane == 0) red[0] = t;
    }
    __syncthreads();
    float inv = rsqrtf(red[0] / (float)HDIM + 1e-5f);
    float* orow = o + (size_t)row*HDIM;
    for (int c = threadIdx.x; c < HDIM; c += blockDim.x) orow[c] = xr[c] * inv * w[c];
}

// ------------------------- TF32 tensor-core GEMM (NT), pipelined -------------------------
// C[M,N] = A[M,K] @ B[N,K]^T (+R), fp32 in/out, tf32 MMA.
// smem layout per 128x16 tile: element k of row r lives at
//   r*16 + ((k&3) ^ swz(r))*4 + (k>>2),   swz(r) = (r&3) ^ ((r>>2)&1)
// -> one LDS.128 per lane yields fragments for BOTH k8 MMA steps, conflict-free.
#define BM 128
#define BN 128
#define BK 16
#define TILEF (128*16)    // floats per operand tile

__device__ __forceinline__ float f2tf32(float f) {
    unsigned r;
    asm("cvt.rna.tf32.f32 %0, %1;" : "=r"(r) : "f"(f));
    return __uint_as_float(r);
}

__device__ __forceinline__ void mma_tf32(float c[4], float2 alo, float2 ahi, float2 b) {
    asm volatile(
        "mma.sync.aligned.m16n8k8.row.col.f32.tf32.tf32.f32 "
        "{%0,%1,%2,%3}, {%4,%5,%6,%7}, {%8,%9}, {%0,%1,%2,%3};\n"
        : "+f"(c[0]), "+f"(c[1]), "+f"(c[2]), "+f"(c[3])
        : "r"(__float_as_uint(alo.x)), "r"(__float_as_uint(ahi.x)),
          "r"(__float_as_uint(alo.y)), "r"(__float_as_uint(ahi.y)),
          "r"(__float_as_uint(b.x)),   "r"(__float_as_uint(b.y)));
}

__device__ __forceinline__ float4 gload_row(const float* __restrict__ P,
                                            int r0, int Rend, int K, int ks, int fid) {
    int row = fid >> 2, c4 = fid & 3;
    int gr = r0 + row;
    if (gr < Rend) return *(const float4*)(P + (size_t)gr*K + ks + (c4 << 2));
    return make_float4(0.f, 0.f, 0.f, 0.f);
}

__device__ __forceinline__ void sstore_sw(float* __restrict__ S, int fid, float4 v) {
    int row = fid >> 2, c4 = fid & 3;
    int swz = (row & 3) ^ ((row >> 2) & 1);
    float* d = S + row*16 + c4;
    d[((0 ^ swz) << 2)] = f2tf32(v.x);
    d[((1 ^ swz) << 2)] = f2tf32(v.y);
    d[((2 ^ swz) << 2)] = f2tf32(v.z);
    d[((3 ^ swz) << 2)] = f2tf32(v.w);
}

__device__ __forceinline__ void gemm_tf32_body(
    const float* __restrict__ A, const float* __restrict__ B,
    float* __restrict__ C, const float* __restrict__ R,
    int m0, int Mend, int n0, int N, int K)
{
    __shared__ float As[2*TILEF];
    __shared__ float Bs[2*TILEF];
    int tid = threadIdx.x;
    int lane = tid & 31, wid = tid >> 5;
    int wm = (wid & 1) * 64;       // 2 warps over M
    int wn = (wid >> 1) * 32;      // 4 warps over N
    int tig = lane & 3, grp = lane >> 2;
    int swzL = (grp & 3) ^ ((grp >> 2) & 1);
    int chunk = ((tig ^ swzL) << 2);

    float acc[4][4][4];
#pragma unroll
    for (int i = 0; i < 4; i++)
#pragma unroll
        for (int j = 0; j < 4; j++)
#pragma unroll
            for (int r = 0; r < 4; r++) acc[i][j][r] = 0.f;

    int fid0 = tid, fid1 = tid + 256;
    int nT = K / BK;

    // prologue: tile 0 -> buffer 0
    {
        float4 a0 = gload_row(A, m0, Mend, K, 0, fid0);
        float4 a1 = gload_row(A, m0, Mend, K, 0, fid1);
        float4 b0 = gload_row(B, n0, N,    K, 0, fid0);
        float4 b1 = gload_row(B, n0, N,    K, 0, fid1);
        sstore_sw(As, fid0, a0); sstore_sw(As, fid1, a1);
        sstore_sw(Bs, fid0, b0); sstore_sw(Bs, fid1, b1);
    }
    __syncthreads();

    for (int t = 0; t < nT; t++) {
        const float* curA = As + (t & 1) * TILEF;
        const float* curB = Bs + (t & 1) * TILEF;
        float4 pa0, pa1, pb0, pb1;
        bool more = (t + 1 < nT);
        if (more) {
            int ks = (t + 1) * BK;
            pa0 = gload_row(A, m0, Mend, K, ks, fid0);
            pa1 = gload_row(A, m0, Mend, K, ks, fid1);
            pb0 = gload_row(B, n0, N,    K, ks, fid0);
            pb1 = gload_row(B, n0, N,    K, ks, fid1);
        }

        // compute on current buffers
        float4 bq[4];
#pragma unroll
        for (int j = 0; j < 4; j++)
            bq[j] = *(const float4*)&curB[(wn + j*8 + grp)*16 + chunk];
#pragma unroll
        for (int i = 0; i < 4; i++) {
            int ra = (wm + i*16 + grp)*16 + chunk;
            float4 alo = *(const float4*)&curA[ra];
            float4 ahi = *(const float4*)&curA[ra + 8*16];
#pragma unroll
            for (int j = 0; j < 4; j++) {
                mma_tf32(acc[i][j], make_float2(alo.x, alo.y),
                         make_float2(ahi.x, ahi.y), make_float2(bq[j].x, bq[j].y));
                mma_tf32(acc[i][j], make_float2(alo.z, alo.w),
                         make_float2(ahi.z, ahi.w), make_float2(bq[j].z, bq[j].w));
            }
        }

        if (more) {
            float* nA = As + ((t + 1) & 1) * TILEF;
            float* nB = Bs + ((t + 1) & 1) * TILEF;
            sstore_sw(nA, fid0, pa0); sstore_sw(nA, fid1, pa1);
            sstore_sw(nB, fid0, pb0); sstore_sw(nB, fid1, pb1);
        }
        __syncthreads();
    }

    // epilogue
#pragma unroll
    for (int i = 0; i < 4; i++) {
#pragma unroll
        for (int j = 0; j < 4; j++) {
            int row = m0 + wm + i*16 + grp;
            int col = n0 + wn + j*8 + tig*2;
            if (col < N) {
                if (row < Mend) {
                    float2 v = make_float2(acc[i][j][0], acc[i][j][1]);
                    if (R) { v.x += R[(size_t)row*N + col]; v.y += R[(size_t)row*N + col+1]; }
                    *(float2*)(C + (size_t)row*N + col) = v;
                }
                if (row + 8 < Mend) {
                    float2 v = make_float2(acc[i][j][2], acc[i][j][3]);
                    if (R) { v.x += R[(size_t)(row+8)*N + col]; v.y += R[(size_t)(row+8)*N + col+1]; }
                    *(float2*)(C + (size_t)(row+8)*N + col) = v;
                }
            }
        }
    }
}

__global__ __launch_bounds__(256, 2) void gemm_tf32_kernel(
    const float* __restrict__ A, const float* __restrict__ B,
    float* __restrict__ C, const float* __restrict__ R, int M, int N, int K) {
    gemm_tf32_body(A, B, C, R, blockIdx.y*BM, M, blockIdx.x*BN, N, K);
}

__global__ __launch_bounds__(256, 2) void gemm_tf32_group_kernel(
    const float* __restrict__ A, const float* __restrict__ Ball,
    float* __restrict__ C, int N, int K) {
    int e = blockIdx.z;
    int mstart = g_off[e], mend = g_off[e+1];
    int m0 = mstart + blockIdx.y*BM;
    if (m0 >= mend) return;
    gemm_tf32_body(A, Ball + (size_t)e*N*K, C, nullptr, m0, mend, blockIdx.x*BN, N, K);
}

// ------------------------- RoPE (in-place on q,k) -------------------------
__global__ void rope_kernel(float* __restrict__ q, float* __restrict__ k) {
    int s  = blockIdx.x;
    int hh = blockIdx.y;
    int d2 = threadIdx.x;   // 0..31
    float* p;
    if (hh < NHEAD) p = q + (size_t)s*(NHEAD*HD) + hh*HD;
    else            p = k + (size_t)s*(NKVH*HD) + (hh-NHEAD)*HD;
    float ps = g_posf[s];
    float inv = powf(10000.f, -((float)d2) / 32.f);
    float ang = ps * inv;
    float sn, cs;
    sincosf(ang, &sn, &cs);
    float x1 = p[d2], x2 = p[d2+32];
    p[d2]    = x1*cs - x2*sn;
    p[d2+32] = x2*cs + x1*sn;
}

// ------------------------- Flash attention (causal, fp32) -------------------------
#define QT 64
#define KT 32
#define APAD 68

__global__ __launch_bounds__(256) void attn_kernel(
    const float* __restrict__ q, const float* __restrict__ k,
    const float* __restrict__ v, float* __restrict__ ctx) {
    __shared__ float Qs[QT][APAD];
    __shared__ float Ks[KT][APAD];
    __shared__ float Vs[KT][APAD];
    int qt = blockIdx.x, h = blockIdx.y;
    int kvh = h >> 2;
    int tid = threadIdx.x;
    int r  = tid >> 2;
    int cg = tid & 3;

#pragma unroll
    for (int l = 0; l < 4; l++) {
        int idx = tid + l*256;
        int rr = idx >> 4, dq = (idx & 15) << 2;
        *(float4*)&Qs[rr][dq] =
            *(const float4*)(q + (size_t)(qt*QT+rr)*(NHEAD*HD) + h*HD + dq);
    }
    __syncthreads();

    float m = -INFINITY, l = 0.f;
    float o[64];
#pragma unroll
    for (int d = 0; d < 64; d++) o[d] = 0.f;

    int jmax = 2*qt + 1;
    int qrow = qt*QT + r;
    for (int j = 0; j <= jmax; j++) {
#pragma unroll
        for (int lq = 0; lq < 2; lq++) {
            int idx = tid + lq*256;
            int rr = idx >> 4, dq = (idx & 15) << 2;
            size_t goff = (size_t)(j*KT+rr)*(NKVH*HD) + kvh*HD + dq;
            *(float4*)&Ks[rr][dq] = *(const float4*)(k + goff);
            *(float4*)&Vs[rr][dq] = *(const float4*)(v + goff);
        }
        __syncthreads();

        float s[8];
#pragma unroll
        for (int jj = 0; jj < 8; jj++) s[jj] = 0.f;
        const float4* Q4 = (const float4*)&Qs[r][0];
#pragma unroll 4
        for (int d4 = 0; d4 < 16; d4++) {
            float4 q4 = Q4[d4];
#pragma unroll
            for (int jj = 0; jj < 8; jj++) {
                int c = cg + 4*jj;
                float4 k4 = *(const float4*)&Ks[c][d4 << 2];
                s[jj] += q4.x*k4.x + q4.y*k4.y + q4.z*k4.z + q4.w*k4.w;
            }
        }
        float mloc = -INFINITY;
#pragma unroll
        for (int jj = 0; jj < 8; jj++) {
            s[jj] *= 0.125f;
            int kk = j*KT + cg + 4*jj;
            if (kk > qrow) s[jj] = -1e30f;
            mloc = fmaxf(mloc, s[jj]);
        }
        mloc = fmaxf(mloc, __shfl_xor_sync(0xffffffffu, mloc, 1));
        mloc = fmaxf(mloc, __shfl_xor_sync(0xffffffffu, mloc, 2));
        float mnew = fmaxf(m, mloc);
        float scale = __expf(m - mnew);
        float p[8]; float psum = 0.f;
#pragma unroll
        for (int jj = 0; jj < 8; jj++) { p[jj] = __expf(s[jj] - mnew); psum += p[jj]; }
        psum += __shfl_xor_sync(0xffffffffu, psum, 1);
        psum += __shfl_xor_sync(0xffffffffu, psum, 2);
        l = l*scale + psum;
        m = mnew;
#pragma unroll
        for (int d = 0; d < 64; d++) o[d] *= scale;
#pragma unroll
        for (int jj = 0; jj < 8; jj++) {
            int c = cg + 4*jj;
            float pj = p[jj];
            const float4* V4 = (const float4*)&Vs[c][0];
#pragma unroll
            for (int d4 = 0; d4 < 16; d4++) {
                float4 v4 = V4[d4];
                o[d4*4+0] += pj*v4.x; o[d4*4+1] += pj*v4.y;
                o[d4*4+2] += pj*v4.z; o[d4*4+3] += pj*v4.w;
            }
        }
        __syncthreads();
    }
#pragma unroll
    for (int d = 0; d < 64; d++) {
        o[d] += __shfl_xor_sync(0xffffffffu, o[d], 1);
        o[d] += __shfl_xor_sync(0xffffffffu, o[d], 2);
    }
    float invl = 1.f / l;
    size_t base = (size_t)qrow*(NHEAD*HD) + h*HD;
    for (int d = cg*16; d < cg*16 + 16; d++) ctx[base + d] = o[d] * invl;
}

// ------------------------- MoE routing -------------------------
__global__ void reset_kernel() {
    int i = threadIdx.x;
    if (i < NE) { g_cnt[i] = 0; g_cur[i] = 0; }
}

__global__ void router_kernel(const float* __restrict__ x, const float* __restrict__ wg) {
    int t = blockIdx.x;
    int warp = threadIdx.x >> 5, lane = threadIdx.x & 31;
    const float* xr = x + (size_t)t*HDIM;
    const float* wr = wg + (size_t)warp*HDIM;
    float s = 0.f;
    for (int c = lane; c < HDIM; c += 32) s += xr[c]*wr[c];
    for (int off = 16; off; off >>= 1) s += __shfl_xor_sync(0xffffffffu, s, off);
    __shared__ float lg[NE];
    if (lane == 0) lg[warp] = s;
    __syncthreads();
    if (threadIdx.x == 0) {
        int i0 = 0;
        for (int e = 1; e < NE; e++) if (lg[e] > lg[i0]) i0 = e;
        int i1 = (i0 == 0) ? 1 : 0;
        for (int e = 0; e < NE; e++) { if (e == i0) continue; if (lg[e] > lg[i1]) i1 = e; }
        float w0 = 1.f / (1.f + __expf(lg[i1] - lg[i0]));
        for (int e = 0; e < NE; e++) g_rlog[t*NE + e] = lg[e];
        g_tok2e[t*2]   = i0; g_tok2e[t*2+1] = i1;
        g_tok2w[t*2]   = w0; g_tok2w[t*2+1] = 1.f - w0;
        atomicAdd(&g_cnt[i0], 1);
        atomicAdd(&g_cnt[i1], 1);
    }
}

__global__ void scan_kernel() {
    if (threadIdx.x == 0) {
        int acc = 0;
        for (int e = 0; e < NE; e++) { g_off[e] = acc; acc += g_cnt[e]; }
        g_off[NE] = acc;
    }
}

__global__ void scatter_kernel() {
    int t = blockIdx.x*blockDim.x + threadIdx.x;
    if (t >= SQ) return;
#pragma unroll
    for (int sl = 0; sl < 2; sl++) {
        int e = g_tok2e[t*2+sl];
        int rrel = atomicAdd(&g_cur[e], 1);
        int rr = g_off[e] + rrel;
        g_rows[rr] = t;
        g_tok2row[t*2+sl] = rr;
    }
}

__global__ void gather_kernel() {
    int total = SQ*2*(HDIM/4);
    for (int idx = blockIdx.x*blockDim.x + threadIdx.x; idx < total; idx += gridDim.x*blockDim.x) {
        int row = idx / (HDIM/4);
        int c4  = idx % (HDIM/4);
        ((float4*)g_xg)[(size_t)row*(HDIM/4) + c4] =
            ((const float4*)g_xn2)[(size_t)g_rows[row]*(HDIM/4) + c4];
    }
}

__global__ void silu_kernel() {
    size_t total = (size_t)SQ*2*IDIM;
    for (size_t i = blockIdx.x*(size_t)blockDim.x + threadIdx.x; i < total;
         i += (size_t)gridDim.x*blockDim.x) {
        float x = g_b1[i];
        float g = x / (1.f + __expf(-x));
        g_b1[i] = g * g_b3[i];
    }
}

__global__ void finalize_kernel(const float* __restrict__ resid, float* __restrict__ out) {
    int t = blockIdx.x;
    int r0 = g_tok2row[t*2], r1 = g_tok2row[t*2+1];
    float w0 = g_tok2w[t*2], w1 = g_tok2w[t*2+1];
    for (int c = threadIdx.x; c < HDIM; c += blockDim.x) {
        out[(size_t)t*HDIM + c] = resid[(size_t)t*HDIM + c]
            + w0*g_y[(size_t)r0*HDIM + c] + w1*g_y[(size_t)r1*HDIM + c];
    }
}

// ------------------------- output tail writers -------------------------
__global__ void gate_kernel(float* __restrict__ dst, const float* __restrict__ gin) {
    int i = blockIdx.x*blockDim.x + threadIdx.x;
    int total = 4*SQ*NE;
    if (i < total) dst[i] = (i < SQ*NE) ? g_rlog[i] : gin[i];
}

__global__ void posf_kernel(float* __restrict__ dst, int n) {
    int i = blockIdx.x*blockDim.x + threadIdx.x;
    if (i < n) dst[i] = g_posf[i];
}

__global__ void posraw_kernel(float* __restrict__ dst, int n) {
    int i = blockIdx.x*blockDim.x + threadIdx.x;
    if (i < n) ((long long*)dst)[i] = (long long)g_posf[i];
}

__global__ void zerofill_kernel(float* __restrict__ dst, int n) {
    int i = blockIdx.x*blockDim.x + threadIdx.x;
    if (i < n) dst[i] = 0.f;
}

// ------------------------- launch -------------------------
extern "C" void kernel_launch(void* const* d_in, const int* in_sizes, int n_in,
                              void* d_out, int out_size) {
    const float* hidden = (const float*)d_in[0];
    const void*  posraw = d_in[1];
    const float* gatein = (const float*)d_in[2];
    const float* ln1 = (const float*)d_in[3];
    const float* ln2 = (const float*)d_in[4];
    const float* wq  = (const float*)d_in[5];
    const float* wk  = (const float*)d_in[6];
    const float* wv  = (const float*)d_in[7];
    const float* wo  = (const float*)d_in[8];
    const float* wg  = (const float*)d_in[9];
    const float* w1  = (const float*)d_in[10];
    const float* w2  = (const float*)d_in[11];
    const float* w3  = (const float*)d_in[12];

    float *xn1,*q,*k,*v,*ctx,*resid1,*xn2,*xg,*b1,*b3,*y;
    cudaGetSymbolAddress((void**)&xn1,    g_xn1);
    cudaGetSymbolAddress((void**)&q,      g_q);
    cudaGetSymbolAddress((void**)&k,      g_k);
    cudaGetSymbolAddress((void**)&v,      g_v);
    cudaGetSymbolAddress((void**)&ctx,    g_ctx);
    cudaGetSymbolAddress((void**)&resid1, g_resid1);
    cudaGetSymbolAddress((void**)&xn2,    g_xn2);
    cudaGetSymbolAddress((void**)&xg,     g_xg);
    cudaGetSymbolAddress((void**)&b1,     g_b1);
    cudaGetSymbolAddress((void**)&b3,     g_b3);
    cudaGetSymbolAddress((void**)&y,      g_y);

    posdetect_kernel<<<1, 256>>>((const unsigned int*)posraw);
    posconv_kernel<<<SQ/256, 256>>>(posraw);

    // attention path
    rmsnorm_kernel<<<SQ, 256>>>(hidden, ln1, xn1);
    dim3 gq(HDIM/BN, SQ/BM);
    dim3 gkv((NKVH*HD)/BN, SQ/BM);
    gemm_tf32_kernel<<<gq,  256>>>(xn1, wq, q, nullptr, SQ, NHEAD*HD, HDIM);
    gemm_tf32_kernel<<<gkv, 256>>>(xn1, wk, k, nullptr, SQ, NKVH*HD, HDIM);
    gemm_tf32_kernel<<<gkv, 256>>>(xn1, wv, v, nullptr, SQ, NKVH*HD, HDIM);
    rope_kernel<<<dim3(SQ, NHEAD+NKVH), 32>>>(q, k);
    attn_kernel<<<dim3(SQ/QT, NHEAD), 256>>>(q, k, v, ctx);
    gemm_tf32_kernel<<<gq, 256>>>(ctx, wo, resid1, hidden, SQ, HDIM, HDIM);

    // MoE path
    rmsnorm_kernel<<<SQ, 256>>>(resid1, ln2, xn2);
    reset_kernel<<<1, 32>>>();
    router_kernel<<<SQ, 256>>>(xn2, wg);
    scan_kernel<<<1, 32>>>();
    scatter_kernel<<<SQ/256, 256>>>();
    gather_kernel<<<512, 256>>>();
    gemm_tf32_group_kernel<<<dim3(IDIM/BN, SQ/BM, NE), 256>>>(xg, w1, b1, IDIM, HDIM);
    gemm_tf32_group_kernel<<<dim3(IDIM/BN, SQ/BM, NE), 256>>>(xg, w3, b3, IDIM, HDIM);
    silu_kernel<<<2048, 256>>>();
    gemm_tf32_group_kernel<<<dim3(HDIM/BN, SQ/BM, NE), 256>>>(b1, w2, y, HDIM, IDIM);

    float* out = (float*)d_out;
    const int HTOT = SQ*HDIM;
    const int GTOT = 4*SQ*NE;
    finalize_kernel<<<SQ, 256>>>(resid1, out);

    int rem = out_size - HTOT;
    if (rem >= GTOT) {
        gate_kernel<<<(GTOT+255)/256, 256>>>(out + (out_size - GTOT), gatein);
        rem -= GTOT;
    }
    if (rem == SQ) {
        posf_kernel<<<(SQ+255)/256, 256>>>(out + HTOT, SQ);
    } else if (rem == 2*SQ) {
        posraw_kernel<<<(SQ+255)/256, 256>>>(out + HTOT, SQ);
    } else if (rem > 0) {
        zerofill_kernel<<<(rem+255)/256, 256>>>(out + HTOT, rem);
    }
}

// round 5
// speedup vs baseline: 2.1751x; 1.0455x over previous
#include <cuda_runtime.h>
#include <math.h>

#define HDIM 2048
#define SQ   2048
#define NHEAD 32
#define NKVH  8
#define HD    64
#define IDIM  4096
#define NE    8

// ------------------------- scratch (static, no allocs) -------------------------
__device__ float g_xn1[SQ*HDIM];
__device__ float g_q[SQ*NHEAD*HD];
__device__ float g_k[SQ*NKVH*HD];
__device__ float g_v[SQ*NKVH*HD];
__device__ float g_ctx[SQ*NHEAD*HD];
__device__ float g_resid1[SQ*HDIM];
__device__ float g_xn2[SQ*HDIM];
__device__ float g_rlog[SQ*NE];
__device__ int   g_tok2e[SQ*2];
__device__ float g_tok2w[SQ*2];
__device__ int   g_tok2row[SQ*2];
__device__ int   g_rows[SQ*2];
__device__ int   g_cnt[NE];
__device__ int   g_off[NE+1];
__device__ int   g_cur[NE];
__device__ float g_xg[SQ*2*HDIM];
__device__ float g_b1[SQ*2*IDIM];
__device__ float g_b3[SQ*2*IDIM];
__device__ float g_y[SQ*2*HDIM];
__device__ int   g_pos64;
__device__ float g_posf[SQ];

// ------------------------- position width detection -------------------------
__global__ void posdetect_kernel(const unsigned int* __restrict__ p) {
    __shared__ int ok;
    if (threadIdx.x == 0) ok = 1;
    __syncthreads();
    int bad = 0;
    for (int i = threadIdx.x; i < SQ/2; i += blockDim.x)
        if (p[2*i+1] != 0u) bad = 1;
    if (bad) atomicAnd(&ok, 0);
    __syncthreads();
    if (threadIdx.x == 0) g_pos64 = ok;
}

__global__ void posconv_kernel(const void* __restrict__ p) {
    int i = blockIdx.x*blockDim.x + threadIdx.x;
    if (i >= SQ) return;
    long long v = g_pos64 ? ((const long long*)p)[i]
                          : (long long)((const int*)p)[i];
    g_posf[i] = (float)v;
}

// ------------------------- RMSNorm -------------------------
__global__ void rmsnorm_kernel(const float* __restrict__ x, const float* __restrict__ w,
                               float* __restrict__ o) {
    int row = blockIdx.x;
    const float* xr = x + (size_t)row*HDIM;
    float s = 0.f;
    for (int c = threadIdx.x; c < HDIM; c += blockDim.x) { float v = xr[c]; s += v*v; }
    __shared__ float red[8];
    for (int off = 16; off; off >>= 1) s += __shfl_xor_sync(0xffffffffu, s, off);
    int warp = threadIdx.x >> 5, lane = threadIdx.x & 31;
    if (lane == 0) red[warp] = s;
    __syncthreads();
    if (warp == 0) {
        float t = (lane < 8) ? red[lane] : 0.f;
        for (int off = 4; off; off >>= 1) t += __shfl_xor_sync(0xffffffffu, t, off);
        if (lane == 0) red[0] = t;
    }
    __syncthreads();
    float inv = rsqrtf(red[0] / (float)HDIM + 1e-5f);
    float* orow = o + (size_t)row*HDIM;
    for (int c = threadIdx.x; c < HDIM; c += blockDim.x) orow[c] = xr[c] * inv * w[c];
}

// ------------------------- TF32 tensor-core GEMM (NT), pipelined -------------------------
// C[M,N] = A[M,K] @ B[N,K]^T (+R), fp32 in/out, tf32 MMA (raw fp32 operands,
// hardware truncates to tf32 precision -> no cvt instructions in the hot loop).
// smem layout per 128x16 tile: element k of row r at
//   r*16 + ((k&3) ^ swz(r))*4 + (k>>2),   swz(r) = (r&3) ^ ((r>>2)&1)
// -> one LDS.128 per lane yields fragments for BOTH k8 MMA steps, conflict-free.
#define BM 128
#define BN 128
#define BK 16
#define TILEF (128*16)    // floats per operand tile

__device__ __forceinline__ void mma_tf32(float c[4], float2 alo, float2 ahi, float2 b) {
    asm volatile(
        "mma.sync.aligned.m16n8k8.row.col.f32.tf32.tf32.f32 "
        "{%0,%1,%2,%3}, {%4,%5,%6,%7}, {%8,%9}, {%0,%1,%2,%3};\n"
        : "+f"(c[0]), "+f"(c[1]), "+f"(c[2]), "+f"(c[3])
        : "r"(__float_as_uint(alo.x)), "r"(__float_as_uint(ahi.x)),
          "r"(__float_as_uint(alo.y)), "r"(__float_as_uint(ahi.y)),
          "r"(__float_as_uint(b.x)),   "r"(__float_as_uint(b.y)));
}

__device__ __forceinline__ float4 gload_row(const float* __restrict__ P,
                                            int r0, int Rend, int K, int ks, int fid) {
    int row = fid >> 2, c4 = fid & 3;
    int gr = r0 + row;
    if (gr < Rend) return *(const float4*)(P + (size_t)gr*K + ks + (c4 << 2));
    return make_float4(0.f, 0.f, 0.f, 0.f);
}

// raw store into swizzled layout (no cvt; tf32 MMA truncates in HW)
__device__ __forceinline__ void sstore_sw(float* __restrict__ d, int swz, float4 v) {
    d[((0 ^ swz) << 2)] = v.x;
    d[((1 ^ swz) << 2)] = v.y;
    d[((2 ^ swz) << 2)] = v.z;
    d[((3 ^ swz) << 2)] = v.w;
}

__device__ __forceinline__ void gemm_tf32_body(
    const float* __restrict__ A, const float* __restrict__ B,
    float* __restrict__ C, const float* __restrict__ R,
    int m0, int Mend, int n0, int N, int K)
{
    __shared__ float As[2*TILEF];
    __shared__ float Bs[2*TILEF];
    int tid = threadIdx.x;
    int lane = tid & 31, wid = tid >> 5;
    int wm = (wid & 1) * 64;       // 2 warps over M
    int wn = (wid >> 1) * 32;      // 4 warps over N
    int tig = lane & 3, grp = lane >> 2;
    int swzL = (grp & 3) ^ ((grp >> 2) & 1);
    int chunk = ((tig ^ swzL) << 2);

    // hoisted, loop-invariant swizzled store offsets
    int row0 = tid >> 2,          c40 = tid & 3;
    int row1 = (tid + 256) >> 2,  c41 = tid & 3;
    int swz0 = (row0 & 3) ^ ((row0 >> 2) & 1);
    int swz1 = (row1 & 3) ^ ((row1 >> 2) & 1);
    int soff0 = row0*16 + c40;
    int soff1 = row1*16 + c41;

    float acc[4][4][4];
#pragma unroll
    for (int i = 0; i < 4; i++)
#pragma unroll
        for (int j = 0; j < 4; j++)
#pragma unroll
            for (int r = 0; r < 4; r++) acc[i][j][r] = 0.f;

    int fid0 = tid, fid1 = tid + 256;
    int nT = K / BK;

    // prologue: tile 0 -> buffer 0
    {
        float4 a0 = gload_row(A, m0, Mend, K, 0, fid0);
        float4 a1 = gload_row(A, m0, Mend, K, 0, fid1);
        float4 b0 = gload_row(B, n0, N,    K, 0, fid0);
        float4 b1 = gload_row(B, n0, N,    K, 0, fid1);
        sstore_sw(As + soff0, swz0, a0); sstore_sw(As + soff1, swz1, a1);
        sstore_sw(Bs + soff0, swz0, b0); sstore_sw(Bs + soff1, swz1, b1);
    }
    __syncthreads();

    for (int t = 0; t < nT; t++) {
        const float* curA = As + (t & 1) * TILEF;
        const float* curB = Bs + (t & 1) * TILEF;
        float4 pa0, pa1, pb0, pb1;
        bool more = (t + 1 < nT);
        if (more) {
            int ks = (t + 1) * BK;
            pa0 = gload_row(A, m0, Mend, K, ks, fid0);
            pa1 = gload_row(A, m0, Mend, K, ks, fid1);
            pb0 = gload_row(B, n0, N,    K, ks, fid0);
            pb1 = gload_row(B, n0, N,    K, ks, fid1);
        }

        // compute on current buffers
        float4 bq[4];
#pragma unroll
        for (int j = 0; j < 4; j++)
            bq[j] = *(const float4*)&curB[(wn + j*8 + grp)*16 + chunk];
#pragma unroll
        for (int i = 0; i < 4; i++) {
            int ra = (wm + i*16 + grp)*16 + chunk;
            float4 alo = *(const float4*)&curA[ra];
            float4 ahi = *(const float4*)&curA[ra + 8*16];
#pragma unroll
            for (int j = 0; j < 4; j++) {
                mma_tf32(acc[i][j], make_float2(alo.x, alo.y),
                         make_float2(ahi.x, ahi.y), make_float2(bq[j].x, bq[j].y));
                mma_tf32(acc[i][j], make_float2(alo.z, alo.w),
                         make_float2(ahi.z, ahi.w), make_float2(bq[j].z, bq[j].w));
            }
        }

        if (more) {
            float* nA = As + ((t + 1) & 1) * TILEF;
            float* nB = Bs + ((t + 1) & 1) * TILEF;
            sstore_sw(nA + soff0, swz0, pa0); sstore_sw(nA + soff1, swz1, pa1);
            sstore_sw(nB + soff0, swz0, pb0); sstore_sw(nB + soff1, swz1, pb1);
        }
        __syncthreads();
    }

    // epilogue
#pragma unroll
    for (int i = 0; i < 4; i++) {
#pragma unroll
        for (int j = 0; j < 4; j++) {
            int row = m0 + wm + i*16 + grp;
            int col = n0 + wn + j*8 + tig*2;
            if (col < N) {
                if (row < Mend) {
                    float2 v = make_float2(acc[i][j][0], acc[i][j][1]);
                    if (R) { v.x += R[(size_t)row*N + col]; v.y += R[(size_t)row*N + col+1]; }
                    *(float2*)(C + (size_t)row*N + col) = v;
                }
                if (row + 8 < Mend) {
                    float2 v = make_float2(acc[i][j][2], acc[i][j][3]);
                    if (R) { v.x += R[(size_t)(row+8)*N + col]; v.y += R[(size_t)(row+8)*N + col+1]; }
                    *(float2*)(C + (size_t)(row+8)*N + col) = v;
                }
            }
        }
    }
}

__global__ __launch_bounds__(256, 2) void gemm_tf32_kernel(
    const float* __restrict__ A, const float* __restrict__ B,
    float* __restrict__ C, const float* __restrict__ R, int M, int N, int K) {
    gemm_tf32_body(A, B, C, R, blockIdx.y*BM, M, blockIdx.x*BN, N, K);
}

__global__ __launch_bounds__(256, 2) void gemm_tf32_group_kernel(
    const float* __restrict__ A, const float* __restrict__ Ball,
    float* __restrict__ C, int N, int K) {
    int e = blockIdx.z;
    int mstart = g_off[e], mend = g_off[e+1];
    int m0 = mstart + blockIdx.y*BM;
    if (m0 >= mend) return;
    gemm_tf32_body(A, Ball + (size_t)e*N*K, C, nullptr, m0, mend, blockIdx.x*BN, N, K);
}

// ------------------------- RoPE (in-place on q,k) -------------------------
__global__ void rope_kernel(float* __restrict__ q, float* __restrict__ k) {
    int s  = blockIdx.x;
    int hh = blockIdx.y;
    int d2 = threadIdx.x;   // 0..31
    float* p;
    if (hh < NHEAD) p = q + (size_t)s*(NHEAD*HD) + hh*HD;
    else            p = k + (size_t)s*(NKVH*HD) + (hh-NHEAD)*HD;
    float ps = g_posf[s];
    // 10000^(-d2/32) = exp2(-d2 * log2(10000)/32)
    float inv = exp2f(-(float)d2 * 0.41524101186092029f);
    float ang = ps * inv;
    float sn, cs;
    sincosf(ang, &sn, &cs);
    float x1 = p[d2], x2 = p[d2+32];
    p[d2]    = x1*cs - x2*sn;
    p[d2+32] = x2*cs + x1*sn;
}

// ------------------------- Flash attention (causal, fp32) -------------------------
#define QT 64
#define KT 32
#define APAD 68

__global__ __launch_bounds__(256) void attn_kernel(
    const float* __restrict__ q, const float* __restrict__ k,
    const float* __restrict__ v, float* __restrict__ ctx) {
    __shared__ float Qs[QT][APAD];
    __shared__ float Ks[KT][APAD];
    __shared__ float Vs[KT][APAD];
    int qt = blockIdx.x, h = blockIdx.y;
    int kvh = h >> 2;
    int tid = threadIdx.x;
    int r  = tid >> 2;
    int cg = tid & 3;

#pragma unroll
    for (int l = 0; l < 4; l++) {
        int idx = tid + l*256;
        int rr = idx >> 4, dq = (idx & 15) << 2;
        *(float4*)&Qs[rr][dq] =
            *(const float4*)(q + (size_t)(qt*QT+rr)*(NHEAD*HD) + h*HD + dq);
    }
    __syncthreads();

    float m = -INFINITY, l = 0.f;
    float o[64];
#pragma unroll
    for (int d = 0; d < 64; d++) o[d] = 0.f;

    int jmax = 2*qt + 1;
    int qrow = qt*QT + r;
    for (int j = 0; j <= jmax; j++) {
#pragma unroll
        for (int lq = 0; lq < 2; lq++) {
            int idx = tid + lq*256;
            int rr = idx >> 4, dq = (idx & 15) << 2;
            size_t goff = (size_t)(j*KT+rr)*(NKVH*HD) + kvh*HD + dq;
            *(float4*)&Ks[rr][dq] = *(const float4*)(k + goff);
            *(float4*)&Vs[rr][dq] = *(const float4*)(v + goff);
        }
        __syncthreads();

        float s[8];
#pragma unroll
        for (int jj = 0; jj < 8; jj++) s[jj] = 0.f;
        const float4* Q4 = (const float4*)&Qs[r][0];
#pragma unroll 4
        for (int d4 = 0; d4 < 16; d4++) {
            float4 q4 = Q4[d4];
#pragma unroll
            for (int jj = 0; jj < 8; jj++) {
                int c = cg + 4*jj;
                float4 k4 = *(const float4*)&Ks[c][d4 << 2];
                s[jj] += q4.x*k4.x + q4.y*k4.y + q4.z*k4.z + q4.w*k4.w;
            }
        }
        float mloc = -INFINITY;
#pragma unroll
        for (int jj = 0; jj < 8; jj++) {
            s[jj] *= 0.125f;
            int kk = j*KT + cg + 4*jj;
            if (kk > qrow) s[jj] = -1e30f;
            mloc = fmaxf(mloc, s[jj]);
        }
        mloc = fmaxf(mloc, __shfl_xor_sync(0xffffffffu, mloc, 1));
        mloc = fmaxf(mloc, __shfl_xor_sync(0xffffffffu, mloc, 2));
        float mnew = fmaxf(m, mloc);
        float scale = __expf(m - mnew);
        float p[8]; float psum = 0.f;
#pragma unroll
        for (int jj = 0; jj < 8; jj++) { p[jj] = __expf(s[jj] - mnew); psum += p[jj]; }
        psum += __shfl_xor_sync(0xffffffffu, psum, 1);
        psum += __shfl_xor_sync(0xffffffffu, psum, 2);
        l = l*scale + psum;
        m = mnew;
#pragma unroll
        for (int d = 0; d < 64; d++) o[d] *= scale;
#pragma unroll
        for (int jj = 0; jj < 8; jj++) {
            int c = cg + 4*jj;
            float pj = p[jj];
            const float4* V4 = (const float4*)&Vs[c][0];
#pragma unroll
            for (int d4 = 0; d4 < 16; d4++) {
                float4 v4 = V4[d4];
                o[d4*4+0] += pj*v4.x; o[d4*4+1] += pj*v4.y;
                o[d4*4+2] += pj*v4.z; o[d4*4+3] += pj*v4.w;
            }
        }
        __syncthreads();
    }
#pragma unroll
    for (int d = 0; d < 64; d++) {
        o[d] += __shfl_xor_sync(0xffffffffu, o[d], 1);
        o[d] += __shfl_xor_sync(0xffffffffu, o[d], 2);
    }
    float invl = 1.f / l;
    size_t base = (size_t)qrow*(NHEAD*HD) + h*HD;
    for (int d = cg*16; d < cg*16 + 16; d++) ctx[base + d] = o[d] * invl;
}

// ------------------------- MoE routing -------------------------
__global__ void reset_kernel() {
    int i = threadIdx.x;
    if (i < NE) { g_cnt[i] = 0; g_cur[i] = 0; }
}

__global__ void router_kernel(const float* __restrict__ x, const float* __restrict__ wg) {
    int t = blockIdx.x;
    int warp = threadIdx.x >> 5, lane = threadIdx.x & 31;
    const float* xr = x + (size_t)t*HDIM;
    const float* wr = wg + (size_t)warp*HDIM;
    float s = 0.f;
    for (int c = lane; c < HDIM; c += 32) s += xr[c]*wr[c];
    for (int off = 16; off; off >>= 1) s += __shfl_xor_sync(0xffffffffu, s, off);
    __shared__ float lg[NE];
    if (lane == 0) lg[warp] = s;
    __syncthreads();
    if (threadIdx.x == 0) {
        int i0 = 0;
        for (int e = 1; e < NE; e++) if (lg[e] > lg[i0]) i0 = e;
        int i1 = (i0 == 0) ? 1 : 0;
        for (int e = 0; e < NE; e++) { if (e == i0) continue; if (lg[e] > lg[i1]) i1 = e; }
        float w0 = 1.f / (1.f + __expf(lg[i1] - lg[i0]));
        for (int e = 0; e < NE; e++) g_rlog[t*NE + e] = lg[e];
        g_tok2e[t*2]   = i0; g_tok2e[t*2+1] = i1;
        g_tok2w[t*2]   = w0; g_tok2w[t*2+1] = 1.f - w0;
        atomicAdd(&g_cnt[i0], 1);
        atomicAdd(&g_cnt[i1], 1);
    }
}

__global__ void scan_kernel() {
    if (threadIdx.x == 0) {
        int acc = 0;
        for (int e = 0; e < NE; e++) { g_off[e] = acc; acc += g_cnt[e]; }
        g_off[NE] = acc;
    }
}

__global__ void scatter_kernel() {
    int t = blockIdx.x*blockDim.x + threadIdx.x;
    if (t >= SQ) return;
#pragma unroll
    for (int sl = 0; sl < 2; sl++) {
        int e = g_tok2e[t*2+sl];
        int rrel = atomicAdd(&g_cur[e], 1);
        int rr = g_off[e] + rrel;
        g_rows[rr] = t;
        g_tok2row[t*2+sl] = rr;
    }
}

__global__ void gather_kernel() {
    int total = SQ*2*(HDIM/4);
    for (int idx = blockIdx.x*blockDim.x + threadIdx.x; idx < total; idx += gridDim.x*blockDim.x) {
        int row = idx / (HDIM/4);
        int c4  = idx % (HDIM/4);
        ((float4*)g_xg)[(size_t)row*(HDIM/4) + c4] =
            ((const float4*)g_xn2)[(size_t)g_rows[row]*(HDIM/4) + c4];
    }
}

__global__ void silu_kernel() {
    size_t total = (size_t)SQ*2*IDIM;
    for (size_t i = blockIdx.x*(size_t)blockDim.x + threadIdx.x; i < total;
         i += (size_t)gridDim.x*blockDim.x) {
        float x = g_b1[i];
        float g = x / (1.f + __expf(-x));
        g_b1[i] = g * g_b3[i];
    }
}

__global__ void finalize_kernel(const float* __restrict__ resid, float* __restrict__ out) {
    int t = blockIdx.x;
    int r0 = g_tok2row[t*2], r1 = g_tok2row[t*2+1];
    float w0 = g_tok2w[t*2], w1 = g_tok2w[t*2+1];
    for (int c = threadIdx.x; c < HDIM; c += blockDim.x) {
        out[(size_t)t*HDIM + c] = resid[(size_t)t*HDIM + c]
            + w0*g_y[(size_t)r0*HDIM + c] + w1*g_y[(size_t)r1*HDIM + c];
    }
}

// ------------------------- output tail writers -------------------------
__global__ void gate_kernel(float* __restrict__ dst, const float* __restrict__ gin) {
    int i = blockIdx.x*blockDim.x + threadIdx.x;
    int total = 4*SQ*NE;
    if (i < total) dst[i] = (i < SQ*NE) ? g_rlog[i] : gin[i];
}

__global__ void posf_kernel(float* __restrict__ dst, int n) {
    int i = blockIdx.x*blockDim.x + threadIdx.x;
    if (i < n) dst[i] = g_posf[i];
}

__global__ void posraw_kernel(float* __restrict__ dst, int n) {
    int i = blockIdx.x*blockDim.x + threadIdx.x;
    if (i < n) ((long long*)dst)[i] = (long long)g_posf[i];
}

__global__ void zerofill_kernel(float* __restrict__ dst, int n) {
    int i = blockIdx.x*blockDim.x + threadIdx.x;
    if (i < n) dst[i] = 0.f;
}

// ------------------------- launch -------------------------
extern "C" void kernel_launch(void* const* d_in, const int* in_sizes, int n_in,
                              void* d_out, int out_size) {
    const float* hidden = (const float*)d_in[0];
    const void*  posraw = d_in[1];
    const float* gatein = (const float*)d_in[2];
    const float* ln1 = (const float*)d_in[3];
    const float* ln2 = (const float*)d_in[4];
    const float* wq  = (const float*)d_in[5];
    const float* wk  = (const float*)d_in[6];
    const float* wv  = (const float*)d_in[7];
    const float* wo  = (const float*)d_in[8];
    const float* wg  = (const float*)d_in[9];
    const float* w1  = (const float*)d_in[10];
    const float* w2  = (const float*)d_in[11];
    const float* w3  = (const float*)d_in[12];

    float *xn1,*q,*k,*v,*ctx,*resid1,*xn2,*xg,*b1,*b3,*y;
    cudaGetSymbolAddress((void**)&xn1,    g_xn1);
    cudaGetSymbolAddress((void**)&q,      g_q);
    cudaGetSymbolAddress((void**)&k,      g_k);
    cudaGetSymbolAddress((void**)&v,      g_v);
    cudaGetSymbolAddress((void**)&ctx,    g_ctx);
    cudaGetSymbolAddress((void**)&resid1, g_resid1);
    cudaGetSymbolAddress((void**)&xn2,    g_xn2);
    cudaGetSymbolAddress((void**)&xg,     g_xg);
    cudaGetSymbolAddress((void**)&b1,     g_b1);
    cudaGetSymbolAddress((void**)&b3,     g_b3);
    cudaGetSymbolAddress((void**)&y,      g_y);

    posdetect_kernel<<<1, 256>>>((const unsigned int*)posraw);
    posconv_kernel<<<SQ/256, 256>>>(posraw);

    // attention path
    rmsnorm_kernel<<<SQ, 256>>>(hidden, ln1, xn1);
    dim3 gq(HDIM/BN, SQ/BM);
    dim3 gkv((NKVH*HD)/BN, SQ/BM);
    gemm_tf32_kernel<<<gq,  256>>>(xn1, wq, q, nullptr, SQ, NHEAD*HD, HDIM);
    gemm_tf32_kernel<<<gkv, 256>>>(xn1, wk, k, nullptr, SQ, NKVH*HD, HDIM);
    gemm_tf32_kernel<<<gkv, 256>>>(xn1, wv, v, nullptr, SQ, NKVH*HD, HDIM);
    rope_kernel<<<dim3(SQ, NHEAD+NKVH), 32>>>(q, k);
    attn_kernel<<<dim3(SQ/QT, NHEAD), 256>>>(q, k, v, ctx);
    gemm_tf32_kernel<<<gq, 256>>>(ctx, wo, resid1, hidden, SQ, HDIM, HDIM);

    // MoE path
    rmsnorm_kernel<<<SQ, 256>>>(resid1, ln2, xn2);
    reset_kernel<<<1, 32>>>();
    router_kernel<<<SQ, 256>>>(xn2, wg);
    scan_kernel<<<1, 32>>>();
    scatter_kernel<<<SQ/256, 256>>>();
    gather_kernel<<<512, 256>>>();
    gemm_tf32_group_kernel<<<dim3(IDIM/BN, SQ/BM, NE), 256>>>(xg, w1, b1, IDIM, HDIM);
    gemm_tf32_group_kernel<<<dim3(IDIM/BN, SQ/BM, NE), 256>>>(xg, w3, b3, IDIM, HDIM);
    silu_kernel<<<2048, 256>>>();
    gemm_tf32_group_kernel<<<dim3(HDIM/BN, SQ/BM, NE), 256>>>(b1, w2, y, HDIM, IDIM);

    float* out = (float*)d_out;
    const int HTOT = SQ*HDIM;
    const int GTOT = 4*SQ*NE;
    finalize_kernel<<<SQ, 256>>>(resid1, out);

    int rem = out_size - HTOT;
    if (rem >= GTOT) {
        gate_kernel<<<(GTOT+255)/256, 256>>>(out + (out_size - GTOT), gatein);
        rem -= GTOT;
    }
    if (rem == SQ) {
        posf_kernel<<<(SQ+255)/256, 256>>>(out + HTOT, SQ);
    } else if (rem == 2*SQ) {
        posraw_kernel<<<(SQ+255)/256, 256>>>(out + HTOT, SQ);
    } else if (rem > 0) {
        zerofill_kernel<<<(rem+255)/256, 256>>>(out + HTOT, rem);
    }
}

// round 7
// speedup vs baseline: 2.2107x; 1.0164x over previous
#include <cuda_runtime.h>
#include <math.h>

#define HDIM 2048
#define SQ   2048
#define NHEAD 32
#define NKVH  8
#define HD    64
#define IDIM  4096
#define NE    8

// ------------------------- scratch (static, no allocs) -------------------------
__device__ float g_xn1[SQ*HDIM];
__device__ float g_q[SQ*NHEAD*HD];
__device__ float g_k[SQ*NKVH*HD];
__device__ float g_v[SQ*NKVH*HD];
__device__ float g_ctx[SQ*NHEAD*HD];
__device__ float g_resid1[SQ*HDIM];
__device__ float g_xn2[SQ*HDIM];
__device__ float g_rlog[SQ*NE];
__device__ int   g_tok2e[SQ*2];
__device__ float g_tok2w[SQ*2];
__device__ int   g_tok2row[SQ*2];
__device__ int   g_rows[SQ*2];
__device__ int   g_cnt[NE];
__device__ int   g_off[NE+1];
__device__ int   g_cur[NE];
__device__ float g_xg[SQ*2*HDIM];
__device__ float g_b1[SQ*2*IDIM];
__device__ float g_b3[SQ*2*IDIM];
__device__ float g_y[SQ*2*HDIM];
__device__ int   g_pos64;
__device__ float g_posf[SQ];

// tf32 round-to-nearest
__device__ __forceinline__ float f2tf32rn(float f) {
    unsigned r;
    asm("cvt.rna.tf32.f32 %0, %1;" : "=r"(r) : "f"(f));
    return __uint_as_float(r);
}

// ------------------------- position width detection -------------------------
__global__ void posdetect_kernel(const unsigned int* __restrict__ p) {
    __shared__ int ok;
    if (threadIdx.x == 0) ok = 1;
    __syncthreads();
    int bad = 0;
    for (int i = threadIdx.x; i < SQ/2; i += blockDim.x)
        if (p[2*i+1] != 0u) bad = 1;
    if (bad) atomicAnd(&ok, 0);
    __syncthreads();
    if (threadIdx.x == 0) g_pos64 = ok;
}

__global__ void posconv_kernel(const void* __restrict__ p) {
    int i = blockIdx.x*blockDim.x + threadIdx.x;
    if (i >= SQ) return;
    long long v = g_pos64 ? ((const long long*)p)[i]
                          : (long long)((const int*)p)[i];
    g_posf[i] = (float)v;
}

// ------------------------- RMSNorm -------------------------
// do_round=1: output pre-rounded to tf32 (feeds GEMM A only).
// do_round=0: raw fp32 (feeds the router -> must match rounds 3-5 numerics).
__global__ void rmsnorm_kernel(const float* __restrict__ x, const float* __restrict__ w,
                               float* __restrict__ o, int do_round) {
    int row = blockIdx.x;
    const float* xr = x + (size_t)row*HDIM;
    float s = 0.f;
    for (int c = threadIdx.x; c < HDIM; c += blockDim.x) { float v = xr[c]; s += v*v; }
    __shared__ float red[8];
    for (int off = 16; off; off >>= 1) s += __shfl_xor_sync(0xffffffffu, s, off);
    int warp = threadIdx.x >> 5, lane = threadIdx.x & 31;
    if (lane == 0) red[warp] = s;
    __syncthreads();
    if (warp == 0) {
        float t = (lane < 8) ? red[lane] : 0.f;
        for (int off = 4; off; off >>= 1) t += __shfl_xor_sync(0xffffffffu, t, off);
        if (lane == 0) red[0] = t;
    }
    __syncthreads();
    float inv = rsqrtf(red[0] / (float)HDIM + 1e-5f);
    float* orow = o + (size_t)row*HDIM;
    if (do_round) {
        for (int c = threadIdx.x; c < HDIM; c += blockDim.x)
            orow[c] = f2tf32rn(xr[c] * inv * w[c]);
    } else {
        for (int c = threadIdx.x; c < HDIM; c += blockDim.x)
            orow[c] = xr[c] * inv * w[c];
    }
}

// ------------------------- TF32 tensor-core GEMM (NT), pipelined -------------------------
// C[M,N] = A[M,K] @ B[N,K]^T (+R).  A pre-rounded tf32 by its producer;
// B (weights) RN-rounded in-GEMM via cvt.rna.tf32 (8 CVTs/thread/tile).
// smem layout per 128x16 tile: element k of row r at
//   r*16 + ((k&3) ^ swz(r))*4 + (k>>2),   swz(r) = (r&3) ^ ((r>>2)&1)
// -> one LDS.128 per lane yields fragments for BOTH k8 MMA steps, conflict-free.
#define BM 128
#define BN 128
#define BK 16
#define TILEF (128*16)    // floats per operand tile

__device__ __forceinline__ void mma_tf32(float c[4], float2 alo, float2 ahi, float2 b) {
    asm volatile(
        "mma.sync.aligned.m16n8k8.row.col.f32.tf32.tf32.f32 "
        "{%0,%1,%2,%3}, {%4,%5,%6,%7}, {%8,%9}, {%0,%1,%2,%3};\n"
        : "+f"(c[0]), "+f"(c[1]), "+f"(c[2]), "+f"(c[3])
        : "r"(__float_as_uint(alo.x)), "r"(__float_as_uint(ahi.x)),
          "r"(__float_as_uint(alo.y)), "r"(__float_as_uint(ahi.y)),
          "r"(__float_as_uint(b.x)),   "r"(__float_as_uint(b.y)));
}

__device__ __forceinline__ float4 gload_row(const float* __restrict__ P,
                                            int r0, int Rend, int K, int ks, int fid) {
    int row = fid >> 2, c4 = fid & 3;
    int gr = r0 + row;
    if (gr < Rend) return *(const float4*)(P + (size_t)gr*K + ks + (c4 << 2));
    return make_float4(0.f, 0.f, 0.f, 0.f);
}

// raw store into swizzled layout (A side: already tf32-rounded upstream)
__device__ __forceinline__ void sstore_sw(float* __restrict__ d, int swz, float4 v) {
    d[((0 ^ swz) << 2)] = v.x;
    d[((1 ^ swz) << 2)] = v.y;
    d[((2 ^ swz) << 2)] = v.z;
    d[((3 ^ swz) << 2)] = v.w;
}

// B side: cvt.rna.tf32 (the measured-good round-4 path)
__device__ __forceinline__ void sstore_sw_cvt(float* __restrict__ d, int swz, float4 v) {
    d[((0 ^ swz) << 2)] = f2tf32rn(v.x);
    d[((1 ^ swz) << 2)] = f2tf32rn(v.y);
    d[((2 ^ swz) << 2)] = f2tf32rn(v.z);
    d[((3 ^ swz) << 2)] = f2tf32rn(v.w);
}

__device__ __forceinline__ void gemm_tf32_body(
    const float* __restrict__ A, const float* __restrict__ B,
    float* __restrict__ C, const float* __restrict__ R,
    int m0, int Mend, int n0, int N, int K)
{
    __shared__ float As[2*TILEF];
    __shared__ float Bs[2*TILEF];
    int tid = threadIdx.x;
    int lane = tid & 31, wid = tid >> 5;
    int wm = (wid & 1) * 64;       // 2 warps over M
    int wn = (wid >> 1) * 32;      // 4 warps over N
    int tig = lane & 3, grp = lane >> 2;
    int swzL = (grp & 3) ^ ((grp >> 2) & 1);
    int chunk = ((tig ^ swzL) << 2);

    // hoisted, loop-invariant swizzled store offsets
    int row0 = tid >> 2,          c40 = tid & 3;
    int row1 = (tid + 256) >> 2,  c41 = tid & 3;
    int swz0 = (row0 & 3) ^ ((row0 >> 2) & 1);
    int swz1 = (row1 & 3) ^ ((row1 >> 2) & 1);
    int soff0 = row0*16 + c40;
    int soff1 = row1*16 + c41;

    float acc[4][4][4];
#pragma unroll
    for (int i = 0; i < 4; i++)
#pragma unroll
        for (int j = 0; j < 4; j++)
#pragma unroll
            for (int r = 0; r < 4; r++) acc[i][j][r] = 0.f;

    int fid0 = tid, fid1 = tid + 256;
    int nT = K / BK;

    // prologue: tile 0 -> buffer 0
    {
        float4 a0 = gload_row(A, m0, Mend, K, 0, fid0);
        float4 a1 = gload_row(A, m0, Mend, K, 0, fid1);
        float4 b0 = gload_row(B, n0, N,    K, 0, fid0);
        float4 b1 = gload_row(B, n0, N,    K, 0, fid1);
        sstore_sw(As + soff0, swz0, a0);     sstore_sw(As + soff1, swz1, a1);
        sstore_sw_cvt(Bs + soff0, swz0, b0); sstore_sw_cvt(Bs + soff1, swz1, b1);
    }
    __syncthreads();

    for (int t = 0; t < nT; t++) {
        const float* curA = As + (t & 1) * TILEF;
        const float* curB = Bs + (t & 1) * TILEF;
        float4 pa0, pa1, pb0, pb1;
        bool more = (t + 1 < nT);
        if (more) {
            int ks = (t + 1) * BK;
            pa0 = gload_row(A, m0, Mend, K, ks, fid0);
            pa1 = gload_row(A, m0, Mend, K, ks, fid1);
            pb0 = gload_row(B, n0, N,    K, ks, fid0);
            pb1 = gload_row(B, n0, N,    K, ks, fid1);
        }

        // compute on current buffers
        float4 bq[4];
#pragma unroll
        for (int j = 0; j < 4; j++)
            bq[j] = *(const float4*)&curB[(wn + j*8 + grp)*16 + chunk];
#pragma unroll
        for (int i = 0; i < 4; i++) {
            int ra = (wm + i*16 + grp)*16 + chunk;
            float4 alo = *(const float4*)&curA[ra];
            float4 ahi = *(const float4*)&curA[ra + 8*16];
#pragma unroll
            for (int j = 0; j < 4; j++) {
                mma_tf32(acc[i][j], make_float2(alo.x, alo.y),
                         make_float2(ahi.x, ahi.y), make_float2(bq[j].x, bq[j].y));
                mma_tf32(acc[i][j], make_float2(alo.z, alo.w),
                         make_float2(ahi.z, ahi.w), make_float2(bq[j].z, bq[j].w));
            }
        }

        if (more) {
            float* nA = As + ((t + 1) & 1) * TILEF;
            float* nB = Bs + ((t + 1) & 1) * TILEF;
            sstore_sw(nA + soff0, swz0, pa0);     sstore_sw(nA + soff1, swz1, pa1);
            sstore_sw_cvt(nB + soff0, swz0, pb0); sstore_sw_cvt(nB + soff1, swz1, pb1);
        }
        __syncthreads();
    }

    // epilogue
#pragma unroll
    for (int i = 0; i < 4; i++) {
#pragma unroll
        for (int j = 0; j < 4; j++) {
            int row = m0 + wm + i*16 + grp;
            int col = n0 + wn + j*8 + tig*2;
            if (col < N) {
                if (row < Mend) {
                    float2 v = make_float2(acc[i][j][0], acc[i][j][1]);
                    if (R) { v.x += R[(size_t)row*N + col]; v.y += R[(size_t)row*N + col+1]; }
                    *(float2*)(C + (size_t)row*N + col) = v;
                }
                if (row + 8 < Mend) {
                    float2 v = make_float2(acc[i][j][2], acc[i][j][3]);
                    if (R) { v.x += R[(size_t)(row+8)*N + col]; v.y += R[(size_t)(row+8)*N + col+1]; }
                    *(float2*)(C + (size_t)(row+8)*N + col) = v;
                }
            }
        }
    }
}

__global__ __launch_bounds__(256, 2) void gemm_tf32_kernel(
    const float* __restrict__ A, const float* __restrict__ B,
    float* __restrict__ C, const float* __restrict__ R, int M, int N, int K) {
    gemm_tf32_body(A, B, C, R, blockIdx.y*BM, M, blockIdx.x*BN, N, K);
}

// merged QKV: one grid covering N = 2048 (q) + 512 (k) + 512 (v)
__global__ __launch_bounds__(256, 2) void gemm_qkv_kernel(
    const float* __restrict__ A,
    const float* __restrict__ wq, const float* __restrict__ wk, const float* __restrict__ wv) {
    int nb = blockIdx.x;   // 0..23
    const float* B; float* C; int n0, N;
    if (nb < 16)      { B = wq; C = g_q; n0 = nb*BN;       N = NHEAD*HD; }
    else if (nb < 20) { B = wk; C = g_k; n0 = (nb-16)*BN;  N = NKVH*HD;  }
    else              { B = wv; C = g_v; n0 = (nb-20)*BN;  N = NKVH*HD;  }
    gemm_tf32_body(A, B, C, nullptr, blockIdx.y*BM, SQ, n0, N, HDIM);
}

__global__ __launch_bounds__(256, 2) void gemm_tf32_group_kernel(
    const float* __restrict__ A, const float* __restrict__ Ball,
    float* __restrict__ C, int N, int K) {
    int e = blockIdx.z;
    int mstart = g_off[e], mend = g_off[e+1];
    int m0 = mstart + blockIdx.y*BM;
    if (m0 >= mend) return;
    gemm_tf32_body(A, Ball + (size_t)e*N*K, C, nullptr, m0, mend, blockIdx.x*BN, N, K);
}

// ------------------------- RoPE (in-place on q,k) -------------------------
__global__ void rope_kernel(float* __restrict__ q, float* __restrict__ k) {
    int s  = blockIdx.x;
    int hh = blockIdx.y;
    int d2 = threadIdx.x;   // 0..31
    float* p;
    if (hh < NHEAD) p = q + (size_t)s*(NHEAD*HD) + hh*HD;
    else            p = k + (size_t)s*(NKVH*HD) + (hh-NHEAD)*HD;
    float ps = g_posf[s];
    float inv = exp2f(-(float)d2 * 0.41524101186092029f);
    float ang = ps * inv;
    float sn, cs;
    sincosf(ang, &sn, &cs);
    float x1 = p[d2], x2 = p[d2+32];
    p[d2]    = x1*cs - x2*sn;
    p[d2+32] = x2*cs + x1*sn;
}

// ------------------------- Flash attention (causal, fp32) -------------------------
#define QT 64
#define KT 32
#define APAD 68

__global__ __launch_bounds__(256) void attn_kernel(
    const float* __restrict__ q, const float* __restrict__ k,
    const float* __restrict__ v, float* __restrict__ ctx) {
    __shared__ float Qs[QT][APAD];
    __shared__ float Ks[KT][APAD];
    __shared__ float Vs[KT][APAD];
    int qt = blockIdx.x, h = blockIdx.y;
    int kvh = h >> 2;
    int tid = threadIdx.x;
    int r  = tid >> 2;
    int cg = tid & 3;

#pragma unroll
    for (int l = 0; l < 4; l++) {
        int idx = tid + l*256;
        int rr = idx >> 4, dq = (idx & 15) << 2;
        *(float4*)&Qs[rr][dq] =
            *(const float4*)(q + (size_t)(qt*QT+rr)*(NHEAD*HD) + h*HD + dq);
    }
    __syncthreads();

    float m = -INFINITY, l = 0.f;
    float o[64];
#pragma unroll
    for (int d = 0; d < 64; d++) o[d] = 0.f;

    int jmax = 2*qt + 1;
    int qrow = qt*QT + r;
    for (int j = 0; j <= jmax; j++) {
#pragma unroll
        for (int lq = 0; lq < 2; lq++) {
            int idx = tid + lq*256;
            int rr = idx >> 4, dq = (idx & 15) << 2;
            size_t goff = (size_t)(j*KT+rr)*(NKVH*HD) + kvh*HD + dq;
            *(float4*)&Ks[rr][dq] = *(const float4*)(k + goff);
            *(float4*)&Vs[rr][dq] = *(const float4*)(v + goff);
        }
        __syncthreads();

        float s[8];
#pragma unroll
        for (int jj = 0; jj < 8; jj++) s[jj] = 0.f;
        const float4* Q4 = (const float4*)&Qs[r][0];
#pragma unroll 4
        for (int d4 = 0; d4 < 16; d4++) {
            float4 q4 = Q4[d4];
#pragma unroll
            for (int jj = 0; jj < 8; jj++) {
                int c = cg + 4*jj;
                float4 k4 = *(const float4*)&Ks[c][d4 << 2];
                s[jj] += q4.x*k4.x + q4.y*k4.y + q4.z*k4.z + q4.w*k4.w;
            }
        }
        float mloc = -INFINITY;
#pragma unroll
        for (int jj = 0; jj < 8; jj++) {
            s[jj] *= 0.125f;
            int kk = j*KT + cg + 4*jj;
            if (kk > qrow) s[jj] = -1e30f;
            mloc = fmaxf(mloc, s[jj]);
        }
        mloc = fmaxf(mloc, __shfl_xor_sync(0xffffffffu, mloc, 1));
        mloc = fmaxf(mloc, __shfl_xor_sync(0xffffffffu, mloc, 2));
        float mnew = fmaxf(m, mloc);
        float scale = __expf(m - mnew);
        float p[8]; float psum = 0.f;
#pragma unroll
        for (int jj = 0; jj < 8; jj++) { p[jj] = __expf(s[jj] - mnew); psum += p[jj]; }
        psum += __shfl_xor_sync(0xffffffffu, psum, 1);
        psum += __shfl_xor_sync(0xffffffffu, psum, 2);
        l = l*scale + psum;
        m = mnew;
#pragma unroll
        for (int d = 0; d < 64; d++) o[d] *= scale;
#pragma unroll
        for (int jj = 0; jj < 8; jj++) {
            int c = cg + 4*jj;
            float pj = p[jj];
            const float4* V4 = (const float4*)&Vs[c][0];
#pragma unroll
            for (int d4 = 0; d4 < 16; d4++) {
                float4 v4 = V4[d4];
                o[d4*4+0] += pj*v4.x; o[d4*4+1] += pj*v4.y;
                o[d4*4+2] += pj*v4.z; o[d4*4+3] += pj*v4.w;
            }
        }
        __syncthreads();
    }
#pragma unroll
    for (int d = 0; d < 64; d++) {
        o[d] += __shfl_xor_sync(0xffffffffu, o[d], 1);
        o[d] += __shfl_xor_sync(0xffffffffu, o[d], 2);
    }
    float invl = 1.f / l;
    size_t base = (size_t)qrow*(NHEAD*HD) + h*HD;
    for (int d = cg*16; d < cg*16 + 16; d++)
        ctx[base + d] = f2tf32rn(o[d] * invl);   // ctx feeds o-proj GEMM as A
}

// ------------------------- MoE routing -------------------------
__global__ void reset_kernel() {
    int i = threadIdx.x;
    if (i < NE) { g_cnt[i] = 0; g_cur[i] = 0; }
}

__global__ void router_kernel(const float* __restrict__ x, const float* __restrict__ wg) {
    int t = blockIdx.x;
    int warp = threadIdx.x >> 5, lane = threadIdx.x & 31;
    const float* xr = x + (size_t)t*HDIM;
    const float* wr = wg + (size_t)warp*HDIM;
    float s = 0.f;
    for (int c = lane; c < HDIM; c += 32) s += xr[c]*wr[c];
    for (int off = 16; off; off >>= 1) s += __shfl_xor_sync(0xffffffffu, s, off);
    __shared__ float lg[NE];
    if (lane == 0) lg[warp] = s;
    __syncthreads();
    if (threadIdx.x == 0) {
        int i0 = 0;
        for (int e = 1; e < NE; e++) if (lg[e] > lg[i0]) i0 = e;
        int i1 = (i0 == 0) ? 1 : 0;
        for (int e = 0; e < NE; e++) { if (e == i0) continue; if (lg[e] > lg[i1]) i1 = e; }
        float w0 = 1.f / (1.f + __expf(lg[i1] - lg[i0]));
        for (int e = 0; e < NE; e++) g_rlog[t*NE + e] = lg[e];
        g_tok2e[t*2]   = i0; g_tok2e[t*2+1] = i1;
        g_tok2w[t*2]   = w0; g_tok2w[t*2+1] = 1.f - w0;
        atomicAdd(&g_cnt[i0], 1);
        atomicAdd(&g_cnt[i1], 1);
    }
}

__global__ void scan_kernel() {
    if (threadIdx.x == 0) {
        int acc = 0;
        for (int e = 0; e < NE; e++) { g_off[e] = acc; acc += g_cnt[e]; }
        g_off[NE] = acc;
    }
}

__global__ void scatter_kernel() {
    int t = blockIdx.x*blockDim.x + threadIdx.x;
    if (t >= SQ) return;
#pragma unroll
    for (int sl = 0; sl < 2; sl++) {
        int e = g_tok2e[t*2+sl];
        int rrel = atomicAdd(&g_cur[e], 1);
        int rr = g_off[e] + rrel;
        g_rows[rr] = t;
        g_tok2row[t*2+sl] = rr;
    }
}

// gather applies the tf32 pre-round (xg feeds w1/w3 GEMMs as A);
// router upstream reads the raw xn2, so routing is unperturbed.
__global__ void gather_kernel() {
    int total = SQ*2*(HDIM/4);
    for (int idx = blockIdx.x*blockDim.x + threadIdx.x; idx < total; idx += gridDim.x*blockDim.x) {
        int row = idx / (HDIM/4);
        int c4  = idx % (HDIM/4);
        float4 v = ((const float4*)g_xn2)[(size_t)g_rows[row]*(HDIM/4) + c4];
        v.x = f2tf32rn(v.x); v.y = f2tf32rn(v.y);
        v.z = f2tf32rn(v.z); v.w = f2tf32rn(v.w);
        ((float4*)g_xg)[(size_t)row*(HDIM/4) + c4] = v;
    }
}

__global__ void silu_kernel() {
    size_t total = (size_t)SQ*2*IDIM;
    for (size_t i = blockIdx.x*(size_t)blockDim.x + threadIdx.x; i < total;
         i += (size_t)gridDim.x*blockDim.x) {
        float x = g_b1[i];
        float g = x / (1.f + __expf(-x));
        g_b1[i] = f2tf32rn(g * g_b3[i]);   // feeds w2 GEMM as A
    }
}

__global__ void finalize_kernel(const float* __restrict__ resid, float* __restrict__ out) {
    int t = blockIdx.x;
    int r0 = g_tok2row[t*2], r1 = g_tok2row[t*2+1];
    float w0 = g_tok2w[t*2], w1 = g_tok2w[t*2+1];
    for (int c = threadIdx.x; c < HDIM; c += blockDim.x) {
        out[(size_t)t*HDIM + c] = resid[(size_t)t*HDIM + c]
            + w0*g_y[(size_t)r0*HDIM + c] + w1*g_y[(size_t)r1*HDIM + c];
    }
}

// ------------------------- output tail writers -------------------------
__global__ void gate_kernel(float* __restrict__ dst, const float* __restrict__ gin) {
    int i = blockIdx.x*blockDim.x + threadIdx.x;
    int total = 4*SQ*NE;
    if (i < total) dst[i] = (i < SQ*NE) ? g_rlog[i] : gin[i];
}

__global__ void posf_kernel(float* __restrict__ dst, int n) {
    int i = blockIdx.x*blockDim.x + threadIdx.x;
    if (i < n) dst[i] = g_posf[i];
}

__global__ void posraw_kernel(float* __restrict__ dst, int n) {
    int i = blockIdx.x*blockDim.x + threadIdx.x;
    if (i < n) ((long long*)dst)[i] = (long long)g_posf[i];
}

__global__ void zerofill_kernel(float* __restrict__ dst, int n) {
    int i = blockIdx.x*blockDim.x + threadIdx.x;
    if (i < n) dst[i] = 0.f;
}

// ------------------------- launch -------------------------
extern "C" void kernel_launch(void* const* d_in, const int* in_sizes, int n_in,
                              void* d_out, int out_size) {
    const float* hidden = (const float*)d_in[0];
    const void*  posraw = d_in[1];
    const float* gatein = (const float*)d_in[2];
    const float* ln1 = (const float*)d_in[3];
    const float* ln2 = (const float*)d_in[4];
    const float* wq  = (const float*)d_in[5];
    const float* wk  = (const float*)d_in[6];
    const float* wv  = (const float*)d_in[7];
    const float* wo  = (const float*)d_in[8];
    const float* wg  = (const float*)d_in[9];
    const float* w1  = (const float*)d_in[10];
    const float* w2  = (const float*)d_in[11];
    const float* w3  = (const float*)d_in[12];

    float *xn1,*q,*k,*v,*ctx,*resid1,*xn2,*xg,*b1,*b3,*y;
    cudaGetSymbolAddress((void**)&xn1,    g_xn1);
    cudaGetSymbolAddress((void**)&q,      g_q);
    cudaGetSymbolAddress((void**)&k,      g_k);
    cudaGetSymbolAddress((void**)&v,      g_v);
    cudaGetSymbolAddress((void**)&ctx,    g_ctx);
    cudaGetSymbolAddress((void**)&resid1, g_resid1);
    cudaGetSymbolAddress((void**)&xn2,    g_xn2);
    cudaGetSymbolAddress((void**)&xg,     g_xg);
    cudaGetSymbolAddress((void**)&b1,     g_b1);
    cudaGetSymbolAddress((void**)&b3,     g_b3);
    cudaGetSymbolAddress((void**)&y,      g_y);

    posdetect_kernel<<<1, 256>>>((const unsigned int*)posraw);
    posconv_kernel<<<SQ/256, 256>>>(posraw);

    // attention path
    rmsnorm_kernel<<<SQ, 256>>>(hidden, ln1, xn1, 1);      // rounded (GEMM A only)
    gemm_qkv_kernel<<<dim3(24, SQ/BM), 256>>>(xn1, wq, wk, wv);
    rope_kernel<<<dim3(SQ, NHEAD+NKVH), 32>>>(q, k);
    attn_kernel<<<dim3(SQ/QT, NHEAD), 256>>>(q, k, v, ctx);
    dim3 gq(HDIM/BN, SQ/BM);
    gemm_tf32_kernel<<<gq, 256>>>(ctx, wo, resid1, hidden, SQ, HDIM, HDIM);

    // MoE path
    rmsnorm_kernel<<<SQ, 256>>>(resid1, ln2, xn2, 0);      // RAW (feeds router)
    reset_kernel<<<1, 32>>>();
    router_kernel<<<SQ, 256>>>(xn2, wg);
    scan_kernel<<<1, 32>>>();
    scatter_kernel<<<SQ/256, 256>>>();
    gather_kernel<<<512, 256>>>();
    gemm_tf32_group_kernel<<<dim3(IDIM/BN, SQ/BM, NE), 256>>>(xg, w1, b1, IDIM, HDIM);
    gemm_tf32_group_kernel<<<dim3(IDIM/BN, SQ/BM, NE), 256>>>(xg, w3, b3, IDIM, HDIM);
    silu_kernel<<<2048, 256>>>();
    gemm_tf32_group_kernel<<<dim3(HDIM/BN, SQ/BM, NE), 256>>>(b1, w2, y, HDIM, IDIM);

    float* out = (float*)d_out;
    const int HTOT = SQ*HDIM;
    const int GTOT = 4*SQ*NE;
    finalize_kernel<<<SQ, 256>>>(resid1, out);

    int rem = out_size - HTOT;
    if (rem >= GTOT) {
        gate_kernel<<<(GTOT+255)/256, 256>>>(out + (out_size - GTOT), gatein);
        rem -= GTOT;
    }
    if (rem == SQ) {
        posf_kernel<<<(SQ+255)/256, 256>>>(out + HTOT, SQ);
    } else if (rem == 2*SQ) {
        posraw_kernel<<<(SQ+255)/256, 256>>>(out + HTOT, SQ);
    } else if (rem > 0) {
        zerofill_kernel<<<(rem+255)/256, 256>>>(out + HTOT, rem);
    }
}

// round 9
// speedup vs baseline: 3.1020x; 1.4031x over previous
#include <cuda_runtime.h>
#include <math.h>

#define HDIM 2048
#define SQ   2048
#define NHEAD 32
#define NKVH  8
#define HD    64
#define IDIM  4096
#define NE    8

// ------------------------- scratch (static, no allocs) -------------------------
__device__ float g_xn1[SQ*HDIM];
__device__ float g_q[SQ*NHEAD*HD];
__device__ float g_k[SQ*NKVH*HD];
__device__ float g_v[SQ*NKVH*HD];
__device__ float g_ctx[SQ*NHEAD*HD];
__device__ float g_resid1[SQ*HDIM];
__device__ float g_xn2[SQ*HDIM];
__device__ float g_rlog[SQ*NE];
__device__ int   g_tok2e[SQ*2];
__device__ float g_tok2w[SQ*2];
__device__ int   g_tok2row[SQ*2];
__device__ int   g_rows[SQ*2];
__device__ int   g_cnt[NE];
__device__ int   g_off[NE+1];
__device__ int   g_cur[NE];
__device__ float g_xg[SQ*2*HDIM];
__device__ float g_b1[SQ*2*IDIM];
__device__ float g_b3[SQ*2*IDIM];
__device__ float g_y[SQ*2*HDIM];
__device__ int   g_pos64;
__device__ float g_posf[SQ];

// tf32 round-to-nearest
__device__ __forceinline__ float f2tf32rn(float f) {
    unsigned r;
    asm("cvt.rna.tf32.f32 %0, %1;" : "=r"(r) : "f"(f));
    return __uint_as_float(r);
}

// ------------------------- position width detection -------------------------
__global__ void posdetect_kernel(const unsigned int* __restrict__ p) {
    __shared__ int ok;
    if (threadIdx.x == 0) ok = 1;
    __syncthreads();
    int bad = 0;
    for (int i = threadIdx.x; i < SQ/2; i += blockDim.x)
        if (p[2*i+1] != 0u) bad = 1;
    if (bad) atomicAnd(&ok, 0);
    __syncthreads();
    if (threadIdx.x == 0) g_pos64 = ok;
}

__global__ void posconv_kernel(const void* __restrict__ p) {
    int i = blockIdx.x*blockDim.x + threadIdx.x;
    if (i >= SQ) return;
    long long v = g_pos64 ? ((const long long*)p)[i]
                          : (long long)((const int*)p)[i];
    g_posf[i] = (float)v;
}

// ------------------------- RMSNorm -------------------------
__global__ void rmsnorm_kernel(const float* __restrict__ x, const float* __restrict__ w,
                               float* __restrict__ o, int do_round) {
    int row = blockIdx.x;
    const float* xr = x + (size_t)row*HDIM;
    float s = 0.f;
    for (int c = threadIdx.x; c < HDIM; c += blockDim.x) { float v = xr[c]; s += v*v; }
    __shared__ float red[8];
    for (int off = 16; off; off >>= 1) s += __shfl_xor_sync(0xffffffffu, s, off);
    int warp = threadIdx.x >> 5, lane = threadIdx.x & 31;
    if (lane == 0) red[warp] = s;
    __syncthreads();
    if (warp == 0) {
        float t = (lane < 8) ? red[lane] : 0.f;
        for (int off = 4; off; off >>= 1) t += __shfl_xor_sync(0xffffffffu, t, off);
        if (lane == 0) red[0] = t;
    }
    __syncthreads();
    float inv = rsqrtf(red[0] / (float)HDIM + 1e-5f);
    float* orow = o + (size_t)row*HDIM;
    if (do_round) {
        for (int c = threadIdx.x; c < HDIM; c += blockDim.x)
            orow[c] = f2tf32rn(xr[c] * inv * w[c]);
    } else {
        for (int c = threadIdx.x; c < HDIM; c += blockDim.x)
            orow[c] = xr[c] * inv * w[c];
    }
}

// ------------------------- TF32 HMMA GEMM (NT), pipelined (round-7, proven) ----
#define BM 128
#define BN 128
#define BK 16
#define TILEF (128*16)

__device__ __forceinline__ void mma_tf32(float c[4], float2 alo, float2 ahi, float2 b) {
    asm volatile(
        "mma.sync.aligned.m16n8k8.row.col.f32.tf32.tf32.f32 "
        "{%0,%1,%2,%3}, {%4,%5,%6,%7}, {%8,%9}, {%0,%1,%2,%3};\n"
        : "+f"(c[0]), "+f"(c[1]), "+f"(c[2]), "+f"(c[3])
        : "r"(__float_as_uint(alo.x)), "r"(__float_as_uint(ahi.x)),
          "r"(__float_as_uint(alo.y)), "r"(__float_as_uint(ahi.y)),
          "r"(__float_as_uint(b.x)),   "r"(__float_as_uint(b.y)));
}

__device__ __forceinline__ float4 gload_row(const float* __restrict__ P,
                                            int r0, int Rend, int K, int ks, int fid) {
    int row = fid >> 2, c4 = fid & 3;
    int gr = r0 + row;
    if (gr < Rend) return *(const float4*)(P + (size_t)gr*K + ks + (c4 << 2));
    return make_float4(0.f, 0.f, 0.f, 0.f);
}

__device__ __forceinline__ void sstore_sw(float* __restrict__ d, int swz, float4 v) {
    d[((0 ^ swz) << 2)] = v.x;
    d[((1 ^ swz) << 2)] = v.y;
    d[((2 ^ swz) << 2)] = v.z;
    d[((3 ^ swz) << 2)] = v.w;
}

__device__ __forceinline__ void sstore_sw_cvt(float* __restrict__ d, int swz, float4 v) {
    d[((0 ^ swz) << 2)] = f2tf32rn(v.x);
    d[((1 ^ swz) << 2)] = f2tf32rn(v.y);
    d[((2 ^ swz) << 2)] = f2tf32rn(v.z);
    d[((3 ^ swz) << 2)] = f2tf32rn(v.w);
}

__device__ __forceinline__ void gemm_tf32_body(
    const float* __restrict__ A, const float* __restrict__ B,
    float* __restrict__ C, const float* __restrict__ R,
    int m0, int Mend, int n0, int N, int K)
{
    __shared__ float As[2*TILEF];
    __shared__ float Bs[2*TILEF];
    int tid = threadIdx.x;
    int lane = tid & 31, wid = tid >> 5;
    int wm = (wid & 1) * 64;
    int wn = (wid >> 1) * 32;
    int tig = lane & 3, grp = lane >> 2;
    int swzL = (grp & 3) ^ ((grp >> 2) & 1);
    int chunk = ((tig ^ swzL) << 2);

    int row0 = tid >> 2,          c40 = tid & 3;
    int row1 = (tid + 256) >> 2,  c41 = tid & 3;
    int swz0 = (row0 & 3) ^ ((row0 >> 2) & 1);
    int swz1 = (row1 & 3) ^ ((row1 >> 2) & 1);
    int soff0 = row0*16 + c40;
    int soff1 = row1*16 + c41;

    float acc[4][4][4];
#pragma unroll
    for (int i = 0; i < 4; i++)
#pragma unroll
        for (int j = 0; j < 4; j++)
#pragma unroll
            for (int r = 0; r < 4; r++) acc[i][j][r] = 0.f;

    int fid0 = tid, fid1 = tid + 256;
    int nT = K / BK;

    {
        float4 a0 = gload_row(A, m0, Mend, K, 0, fid0);
        float4 a1 = gload_row(A, m0, Mend, K, 0, fid1);
        float4 b0 = gload_row(B, n0, N,    K, 0, fid0);
        float4 b1 = gload_row(B, n0, N,    K, 0, fid1);
        sstore_sw(As + soff0, swz0, a0);     sstore_sw(As + soff1, swz1, a1);
        sstore_sw_cvt(Bs + soff0, swz0, b0); sstore_sw_cvt(Bs + soff1, swz1, b1);
    }
    __syncthreads();

    for (int t = 0; t < nT; t++) {
        const float* curA = As + (t & 1) * TILEF;
        const float* curB = Bs + (t & 1) * TILEF;
        float4 pa0, pa1, pb0, pb1;
        bool more = (t + 1 < nT);
        if (more) {
            int ks = (t + 1) * BK;
            pa0 = gload_row(A, m0, Mend, K, ks, fid0);
            pa1 = gload_row(A, m0, Mend, K, ks, fid1);
            pb0 = gload_row(B, n0, N,    K, ks, fid0);
            pb1 = gload_row(B, n0, N,    K, ks, fid1);
        }

        float4 bq[4];
#pragma unroll
        for (int j = 0; j < 4; j++)
            bq[j] = *(const float4*)&curB[(wn + j*8 + grp)*16 + chunk];
#pragma unroll
        for (int i = 0; i < 4; i++) {
            int ra = (wm + i*16 + grp)*16 + chunk;
            float4 alo = *(const float4*)&curA[ra];
            float4 ahi = *(const float4*)&curA[ra + 8*16];
#pragma unroll
            for (int j = 0; j < 4; j++) {
                mma_tf32(acc[i][j], make_float2(alo.x, alo.y),
                         make_float2(ahi.x, ahi.y), make_float2(bq[j].x, bq[j].y));
                mma_tf32(acc[i][j], make_float2(alo.z, alo.w),
                         make_float2(ahi.z, ahi.w), make_float2(bq[j].z, bq[j].w));
            }
        }

        if (more) {
            float* nA = As + ((t + 1) & 1) * TILEF;
            float* nB = Bs + ((t + 1) & 1) * TILEF;
            sstore_sw(nA + soff0, swz0, pa0);     sstore_sw(nA + soff1, swz1, pa1);
            sstore_sw_cvt(nB + soff0, swz0, pb0); sstore_sw_cvt(nB + soff1, swz1, pb1);
        }
        __syncthreads();
    }

#pragma unroll
    for (int i = 0; i < 4; i++) {
#pragma unroll
        for (int j = 0; j < 4; j++) {
            int row = m0 + wm + i*16 + grp;
            int col = n0 + wn + j*8 + tig*2;
            if (col < N) {
                if (row < Mend) {
                    float2 v = make_float2(acc[i][j][0], acc[i][j][1]);
                    if (R) { v.x += R[(size_t)row*N + col]; v.y += R[(size_t)row*N + col+1]; }
                    *(float2*)(C + (size_t)row*N + col) = v;
                }
                if (row + 8 < Mend) {
                    float2 v = make_float2(acc[i][j][2], acc[i][j][3]);
                    if (R) { v.x += R[(size_t)(row+8)*N + col]; v.y += R[(size_t)(row+8)*N + col+1]; }
                    *(float2*)(C + (size_t)(row+8)*N + col) = v;
                }
            }
        }
    }
}

__global__ __launch_bounds__(256, 2) void gemm_tf32_kernel(
    const float* __restrict__ A, const float* __restrict__ B,
    float* __restrict__ C, const float* __restrict__ R, int M, int N, int K) {
    gemm_tf32_body(A, B, C, R, blockIdx.y*BM, M, blockIdx.x*BN, N, K);
}

__global__ __launch_bounds__(256, 2) void gemm_qkv_kernel(
    const float* __restrict__ A,
    const float* __restrict__ wq, const float* __restrict__ wk, const float* __restrict__ wv) {
    int nb = blockIdx.x;
    const float* B; float* C; int n0, N;
    if (nb < 16)      { B = wq; C = g_q; n0 = nb*BN;       N = NHEAD*HD; }
    else if (nb < 20) { B = wk; C = g_k; n0 = (nb-16)*BN;  N = NKVH*HD;  }
    else              { B = wv; C = g_v; n0 = (nb-20)*BN;  N = NKVH*HD;  }
    gemm_tf32_body(A, B, C, nullptr, blockIdx.y*BM, SQ, n0, N, HDIM);
}

__global__ __launch_bounds__(256, 2) void gemm_tf32_group_kernel(
    const float* __restrict__ A, const float* __restrict__ Ball,
    float* __restrict__ C, int N, int K) {
    int e = blockIdx.z;
    int mstart = g_off[e], mend = g_off[e+1];
    int m0 = mstart + blockIdx.y*BM;
    if (m0 >= mend) return;
    gemm_tf32_body(A, Ball + (size_t)e*N*K, C, nullptr, m0, mend, blockIdx.x*BN, N, K);
}

// ------------------------- RoPE (in-place, outputs tf32-rounded) -------------------------
__global__ void rope_kernel(float* __restrict__ q, float* __restrict__ k) {
    int s  = blockIdx.x;
    int hh = blockIdx.y;
    int d2 = threadIdx.x;   // 0..31
    float* p;
    if (hh < NHEAD) p = q + (size_t)s*(NHEAD*HD) + hh*HD;
    else            p = k + (size_t)s*(NKVH*HD) + (hh-NHEAD)*HD;
    float ps = g_posf[s];
    float inv = exp2f(-(float)d2 * 0.41524101186092029f);
    float ang = ps * inv;
    float sn, cs;
    sincosf(ang, &sn, &cs);
    float x1 = p[d2], x2 = p[d2+32];
    p[d2]    = f2tf32rn(x1*cs - x2*sn);
    p[d2+32] = f2tf32rn(x2*cs + x1*sn);
}

// ------------------------- Flash attention on tf32 mma.sync -------------------------
// Block: 128 q-rows x 1 head. 8 warps x 16 q-rows; softmax warp-local.
// Smem slab 32KB: phase A = Q staging (128x64 permuted); then
//   K tile  [0..2047]   : 32 kk-rows x 64 d (stride 64, permuted per 16-group)
//   V^T     [2048..4095]: 64 d-rows x 32 kk (stride 32, permuted)
//   P slabs [4096+w*512]: 16 q-rows x 32 kk (stride 32, permuted)
#define AQT 128
#define AKT 32

__global__ __launch_bounds__(256) void attn_mma_kernel(
    const float* __restrict__ q, const float* __restrict__ k,
    const float* __restrict__ v, float* __restrict__ ctx)
{
    __shared__ float sm[8192];
    int bq = blockIdx.x, h = blockIdx.y;
    int kvh = h >> 2;
    int q0 = bq * AQT;
    int tid = threadIdx.x, wid = tid >> 5, lane = tid & 31;
    int tig = lane & 3, grp = lane >> 2;

    // ---- Phase A: stage Q permuted, pull fragments to registers ----
#pragma unroll
    for (int i = 0; i < 8; i++) {
        int fid = tid + i*256;
        int row = fid >> 4, c4 = fid & 15;
        float4 vq = *(const float4*)(q + (size_t)(q0+row)*(NHEAD*HD) + h*HD + (c4 << 2));
        int g = c4 >> 2, sw = (row & 3) ^ ((row >> 2) & 1);
        float* d = &sm[row*64 + g*16 + (c4 & 3)];
        d[((0^sw)<<2)] = vq.x; d[((1^sw)<<2)] = vq.y;
        d[((2^sw)<<2)] = vq.z; d[((3^sw)<<2)] = vq.w;
    }
    __syncthreads();
    int r0 = wid*16 + grp;                       // warp's first q-row (local)
    int swA = (grp & 3) ^ ((grp >> 2) & 1);      // same for r0 and r0+8
    int chA = ((tig ^ swA) << 2);
    float4 qf0[4], qf1[4];
#pragma unroll
    for (int g = 0; g < 4; g++) {
        qf0[g] = *(const float4*)&sm[r0*64 + g*16 + chA];
        qf1[g] = *(const float4*)&sm[(r0+8)*64 + g*16 + chA];
    }
    __syncthreads();

    int qrow0 = q0 + r0, qrow1 = qrow0 + 8;
    float m0 = -INFINITY, m1 = -INFINITY, l0 = 0.f, l1 = 0.f;
    float oa[8][4];
#pragma unroll
    for (int j = 0; j < 8; j++)
#pragma unroll
        for (int r = 0; r < 4; r++) oa[j][r] = 0.f;

    float* pslab = &sm[4096 + wid*512];
    int chP = chA;   // P rows indexed by grp -> same swizzle/chunk as Q frags

    int nkt = 4*bq + 4;
    for (int kt = 0; kt < nkt; kt++) {
        // ---- stage K (permuted) and V^T (transposed+permuted, RN-rounded) ----
#pragma unroll
        for (int i = 0; i < 2; i++) {
            int fid = tid + i*256;
            int row = fid >> 4, c4 = fid & 15;   // kk-row, d-chunk
            size_t goff = (size_t)(kt*AKT + row)*(NKVH*HD) + kvh*HD + (c4 << 2);
            float4 kv4 = *(const float4*)(k + goff);
            int g = c4 >> 2, sw = (row & 3) ^ ((row >> 2) & 1);
            float* d = &sm[row*64 + g*16 + (c4 & 3)];
            d[((0^sw)<<2)] = kv4.x; d[((1^sw)<<2)] = kv4.y;
            d[((2^sw)<<2)] = kv4.z; d[((3^sw)<<2)] = kv4.w;
            float4 vv4 = *(const float4*)(v + goff);
            float vals[4] = {vv4.x, vv4.y, vv4.z, vv4.w};
            int k16 = row & 15;
            int cbase = (row >> 4)*16 + (k16 >> 2);
#pragma unroll
            for (int e = 0; e < 4; e++) {
                int dp = (c4 << 2) + e;
                int sw2 = (dp & 3) ^ ((dp >> 2) & 1);
                sm[2048 + dp*32 + cbase + (((k16 & 3) ^ sw2) << 2)] = f2tf32rn(vals[e]);
            }
        }
        __syncthreads();

        // ---- S = Q K^T ----
        float sc[4][4];
#pragma unroll
        for (int j = 0; j < 4; j++)
#pragma unroll
            for (int r = 0; r < 4; r++) sc[j][r] = 0.f;
#pragma unroll
        for (int j = 0; j < 4; j++) {
            int krow = j*8 + grp;
            int swB = (krow & 3) ^ ((krow >> 2) & 1);
            int chB = ((tig ^ swB) << 2);
#pragma unroll
            for (int g = 0; g < 4; g++) {
                float4 bf = *(const float4*)&sm[krow*64 + g*16 + chB];
                mma_tf32(sc[j], make_float2(qf0[g].x, qf0[g].y),
                         make_float2(qf1[g].x, qf1[g].y), make_float2(bf.x, bf.y));
                mma_tf32(sc[j], make_float2(qf0[g].z, qf0[g].w),
                         make_float2(qf1[g].z, qf1[g].w), make_float2(bf.z, bf.w));
            }
        }

        // ---- mask + scale + online softmax (warp-local) ----
        float lm0 = -INFINITY, lm1 = -INFINITY;
#pragma unroll
        for (int j = 0; j < 4; j++) {
            int col = kt*AKT + j*8 + 2*tig;
            sc[j][0] = (col     <= qrow0) ? sc[j][0]*0.125f : -1e30f;
            sc[j][1] = (col + 1 <= qrow0) ? sc[j][1]*0.125f : -1e30f;
            sc[j][2] = (col     <= qrow1) ? sc[j][2]*0.125f : -1e30f;
            sc[j][3] = (col + 1 <= qrow1) ? sc[j][3]*0.125f : -1e30f;
            lm0 = fmaxf(lm0, fmaxf(sc[j][0], sc[j][1]));
            lm1 = fmaxf(lm1, fmaxf(sc[j][2], sc[j][3]));
        }
        lm0 = fmaxf(lm0, __shfl_xor_sync(0xffffffffu, lm0, 1));
        lm0 = fmaxf(lm0, __shfl_xor_sync(0xffffffffu, lm0, 2));
        lm1 = fmaxf(lm1, __shfl_xor_sync(0xffffffffu, lm1, 1));
        lm1 = fmaxf(lm1, __shfl_xor_sync(0xffffffffu, lm1, 2));
        float mn0 = fmaxf(m0, lm0), mn1 = fmaxf(m1, lm1);
        float s0 = __expf(m0 - mn0), s1 = __expf(m1 - mn1);
        float ps0 = 0.f, ps1 = 0.f;
#pragma unroll
        for (int j = 0; j < 4; j++) {
            sc[j][0] = __expf(sc[j][0] - mn0);
            sc[j][1] = __expf(sc[j][1] - mn0);
            sc[j][2] = __expf(sc[j][2] - mn1);
            sc[j][3] = __expf(sc[j][3] - mn1);
            ps0 += sc[j][0] + sc[j][1];
            ps1 += sc[j][2] + sc[j][3];
        }
        ps0 += __shfl_xor_sync(0xffffffffu, ps0, 1);
        ps0 += __shfl_xor_sync(0xffffffffu, ps0, 2);
        ps1 += __shfl_xor_sync(0xffffffffu, ps1, 1);
        ps1 += __shfl_xor_sync(0xffffffffu, ps1, 2);
        l0 = l0*s0 + ps0; l1 = l1*s1 + ps1;
        m0 = mn0; m1 = mn1;
#pragma unroll
        for (int j = 0; j < 8; j++) {
            oa[j][0] *= s0; oa[j][1] *= s0;
            oa[j][2] *= s1; oa[j][3] *= s1;
        }

        // ---- P -> per-warp slab (permuted, RN-rounded) ----
#pragma unroll
        for (int j = 0; j < 4; j++) {
            int g2 = j >> 1;
            int k16a = (j & 1)*8 + 2*tig;
            int k16b = k16a + 1;
            int c0 = g2*16 + (((k16a & 3) ^ swA) << 2) + (k16a >> 2);
            int c1 = g2*16 + (((k16b & 3) ^ swA) << 2) + (k16b >> 2);
            pslab[grp*32 + c0]     = f2tf32rn(sc[j][0]);
            pslab[grp*32 + c1]     = f2tf32rn(sc[j][1]);
            pslab[(grp+8)*32 + c0] = f2tf32rn(sc[j][2]);
            pslab[(grp+8)*32 + c1] = f2tf32rn(sc[j][3]);
        }
        __syncwarp();
        float4 pf0[2], pf1[2];
#pragma unroll
        for (int g = 0; g < 2; g++) {
            pf0[g] = *(const float4*)&pslab[grp*32 + g*16 + chP];
            pf1[g] = *(const float4*)&pslab[(grp+8)*32 + g*16 + chP];
        }

        // ---- O += P V ----
#pragma unroll
        for (int jd = 0; jd < 8; jd++) {
            int vrow = jd*8 + grp;
            int swV = (vrow & 3) ^ ((vrow >> 2) & 1);
            int chV = ((tig ^ swV) << 2);
#pragma unroll
            for (int g = 0; g < 2; g++) {
                float4 bf = *(const float4*)&sm[2048 + vrow*32 + g*16 + chV];
                mma_tf32(oa[jd], make_float2(pf0[g].x, pf0[g].y),
                         make_float2(pf1[g].x, pf1[g].y), make_float2(bf.x, bf.y));
                mma_tf32(oa[jd], make_float2(pf0[g].z, pf0[g].w),
                         make_float2(pf1[g].z, pf1[g].w), make_float2(bf.z, bf.w));
            }
        }
        __syncthreads();
    }

    // ---- epilogue ----
    float rl0 = 1.f / l0, rl1 = 1.f / l1;
#pragma unroll
    for (int jd = 0; jd < 8; jd++) {
        int dcol = jd*8 + 2*tig;
        float2 v0 = make_float2(f2tf32rn(oa[jd][0]*rl0), f2tf32rn(oa[jd][1]*rl0));
        float2 v1 = make_float2(f2tf32rn(oa[jd][2]*rl1), f2tf32rn(oa[jd][3]*rl1));
        *(float2*)(ctx + (size_t)qrow0*(NHEAD*HD) + h*HD + dcol) = v0;
        *(float2*)(ctx + (size_t)qrow1*(NHEAD*HD) + h*HD + dcol) = v1;
    }
}

// ------------------------- MoE routing -------------------------
__global__ void reset_kernel() {
    int i = threadIdx.x;
    if (i < NE) { g_cnt[i] = 0; g_cur[i] = 0; }
}

__global__ void router_kernel(const float* __restrict__ x, const float* __restrict__ wg) {
    int t = blockIdx.x;
    int warp = threadIdx.x >> 5, lane = threadIdx.x & 31;
    const float* xr = x + (size_t)t*HDIM;
    const float* wr = wg + (size_t)warp*HDIM;
    float s = 0.f;
    for (int c = lane; c < HDIM; c += 32) s += xr[c]*wr[c];
    for (int off = 16; off; off >>= 1) s += __shfl_xor_sync(0xffffffffu, s, off);
    __shared__ float lg[NE];
    if (lane == 0) lg[warp] = s;
    __syncthreads();
    if (threadIdx.x == 0) {
        int i0 = 0;
        for (int e = 1; e < NE; e++) if (lg[e] > lg[i0]) i0 = e;
        int i1 = (i0 == 0) ? 1 : 0;
        for (int e = 0; e < NE; e++) { if (e == i0) continue; if (lg[e] > lg[i1]) i1 = e; }
        float w0 = 1.f / (1.f + __expf(lg[i1] - lg[i0]));
        for (int e = 0; e < NE; e++) g_rlog[t*NE + e] = lg[e];
        g_tok2e[t*2]   = i0; g_tok2e[t*2+1] = i1;
        g_tok2w[t*2]   = w0; g_tok2w[t*2+1] = 1.f - w0;
        atomicAdd(&g_cnt[i0], 1);
        atomicAdd(&g_cnt[i1], 1);
    }
}

__global__ void scan_kernel() {
    if (threadIdx.x == 0) {
        int acc = 0;
        for (int e = 0; e < NE; e++) { g_off[e] = acc; acc += g_cnt[e]; }
        g_off[NE] = acc;
    }
}

__global__ void scatter_kernel() {
    int t = blockIdx.x*blockDim.x + threadIdx.x;
    if (t >= SQ) return;
#pragma unroll
    for (int sl = 0; sl < 2; sl++) {
        int e = g_tok2e[t*2+sl];
        int rrel = atomicAdd(&g_cur[e], 1);
        int rr = g_off[e] + rrel;
        g_rows[rr] = t;
        g_tok2row[t*2+sl] = rr;
    }
}

__global__ void gather_kernel() {
    int total = SQ*2*(HDIM/4);
    for (int idx = blockIdx.x*blockDim.x + threadIdx.x; idx < total; idx += gridDim.x*blockDim.x) {
        int row = idx / (HDIM/4);
        int c4  = idx % (HDIM/4);
        float4 v = ((const float4*)g_xn2)[(size_t)g_rows[row]*(HDIM/4) + c4];
        v.x = f2tf32rn(v.x); v.y = f2tf32rn(v.y);
        v.z = f2tf32rn(v.z); v.w = f2tf32rn(v.w);
        ((float4*)g_xg)[(size_t)row*(HDIM/4) + c4] = v;
    }
}

__global__ void silu_kernel() {
    size_t total = (size_t)SQ*2*IDIM;
    for (size_t i = blockIdx.x*(size_t)blockDim.x + threadIdx.x; i < total;
         i += (size_t)gridDim.x*blockDim.x) {
        float x = g_b1[i];
        float g = x / (1.f + __expf(-x));
        g_b1[i] = f2tf32rn(g * g_b3[i]);
    }
}

__global__ void finalize_kernel(const float* __restrict__ resid, float* __restrict__ out) {
    int t = blockIdx.x;
    int r0 = g_tok2row[t*2], r1 = g_tok2row[t*2+1];
    float w0 = g_tok2w[t*2], w1 = g_tok2w[t*2+1];
    for (int c = threadIdx.x; c < HDIM; c += blockDim.x) {
        out[(size_t)t*HDIM + c] = resid[(size_t)t*HDIM + c]
            + w0*g_y[(size_t)r0*HDIM + c] + w1*g_y[(size_t)r1*HDIM + c];
    }
}

// ------------------------- output tail writers -------------------------
__global__ void gate_kernel(float* __restrict__ dst, const float* __restrict__ gin) {
    int i = blockIdx.x*blockDim.x + threadIdx.x;
    int total = 4*SQ*NE;
    if (i < total) dst[i] = (i < SQ*NE) ? g_rlog[i] : gin[i];
}

__global__ void posf_kernel(float* __restrict__ dst, int n) {
    int i = blockIdx.x*blockDim.x + threadIdx.x;
    if (i < n) dst[i] = g_posf[i];
}

__global__ void posraw_kernel(float* __restrict__ dst, int n) {
    int i = blockIdx.x*blockDim.x + threadIdx.x;
    if (i < n) ((long long*)dst)[i] = (long long)g_posf[i];
}

__global__ void zerofill_kernel(float* __restrict__ dst, int n) {
    int i = blockIdx.x*blockDim.x + threadIdx.x;
    if (i < n) dst[i] = 0.f;
}

// ------------------------- launch -------------------------
extern "C" void kernel_launch(void* const* d_in, const int* in_sizes, int n_in,
                              void* d_out, int out_size) {
    const float* hidden = (const float*)d_in[0];
    const void*  posraw = d_in[1];
    const float* gatein = (const float*)d_in[2];
    const float* ln1 = (const float*)d_in[3];
    const float* ln2 = (const float*)d_in[4];
    const float* wq  = (const float*)d_in[5];
    const float* wk  = (const float*)d_in[6];
    const float* wv  = (const float*)d_in[7];
    const float* wo  = (const float*)d_in[8];
    const float* wg  = (const float*)d_in[9];
    const float* w1  = (const float*)d_in[10];
    const float* w2  = (const float*)d_in[11];
    const float* w3  = (const float*)d_in[12];

    float *xn1,*q,*k,*v,*ctx,*resid1,*xn2,*xg,*b1,*b3,*y;
    cudaGetSymbolAddress((void**)&xn1,    g_xn1);
    cudaGetSymbolAddress((void**)&q,      g_q);
    cudaGetSymbolAddress((void**)&k,      g_k);
    cudaGetSymbolAddress((void**)&v,      g_v);
    cudaGetSymbolAddress((void**)&ctx,    g_ctx);
    cudaGetSymbolAddress((void**)&resid1, g_resid1);
    cudaGetSymbolAddress((void**)&xn2,    g_xn2);
    cudaGetSymbolAddress((void**)&xg,     g_xg);
    cudaGetSymbolAddress((void**)&b1,     g_b1);
    cudaGetSymbolAddress((void**)&b3,     g_b3);
    cudaGetSymbolAddress((void**)&y,      g_y);

    posdetect_kernel<<<1, 256>>>((const unsigned int*)posraw);
    posconv_kernel<<<SQ/256, 256>>>(posraw);

    // attention path
    rmsnorm_kernel<<<SQ, 256>>>(hidden, ln1, xn1, 1);
    gemm_qkv_kernel<<<dim3(24, SQ/BM), 256>>>(xn1, wq, wk, wv);
    rope_kernel<<<dim3(SQ, NHEAD+NKVH), 32>>>(q, k);
    attn_mma_kernel<<<dim3(SQ/AQT, NHEAD), 256>>>(q, k, v, ctx);
    dim3 gq(HDIM/BN, SQ/BM);
    gemm_tf32_kernel<<<gq, 256>>>(ctx, wo, resid1, hidden, SQ, HDIM, HDIM);

    // MoE path
    rmsnorm_kernel<<<SQ, 256>>>(resid1, ln2, xn2, 0);
    reset_kernel<<<1, 32>>>();
    router_kernel<<<SQ, 256>>>(xn2, wg);
    scan_kernel<<<1, 32>>>();
    scatter_kernel<<<SQ/256, 256>>>();
    gather_kernel<<<512, 256>>>();
    gemm_tf32_group_kernel<<<dim3(IDIM/BN, SQ/BM, NE), 256>>>(xg, w1, b1, IDIM, HDIM);
    gemm_tf32_group_kernel<<<dim3(IDIM/BN, SQ/BM, NE), 256>>>(xg, w3, b3, IDIM, HDIM);
    silu_kernel<<<2048, 256>>>();
    gemm_tf32_group_kernel<<<dim3(HDIM/BN, SQ/BM, NE), 256>>>(b1, w2, y, HDIM, IDIM);

    float* out = (float*)d_out;
    const int HTOT = SQ*HDIM;
    const int GTOT = 4*SQ*NE;
    finalize_kernel<<<SQ, 256>>>(resid1, out);

    int rem = out_size - HTOT;
    if (rem >= GTOT) {
        gate_kernel<<<(GTOT+255)/256, 256>>>(out + (out_size - GTOT), gatein);
        rem -= GTOT;
    }
    if (rem == SQ) {
        posf_kernel<<<(SQ+255)/256, 256>>>(out + HTOT, SQ);
    } else if (rem == 2*SQ) {
        posraw_kernel<<<(SQ+255)/256, 256>>>(out + HTOT, SQ);
    } else if (rem > 0) {
        zerofill_kernel<<<(rem+255)/256, 256>>>(out + HTOT, rem);
    }
}

// round 10
// speedup vs baseline: 3.5553x; 1.1461x over previous
#include <cuda_runtime.h>
#include <math.h>

#define HDIM 2048
#define SQ   2048
#define NHEAD 32
#define NKVH  8
#define HD    64
#define IDIM  4096
#define NE    8

// ------------------------- scratch (static, no allocs) -------------------------
__device__ float g_xn1[SQ*HDIM];
__device__ float g_q[SQ*NHEAD*HD];
__device__ float g_k[SQ*NKVH*HD];
__device__ float g_v[SQ*NKVH*HD];
__device__ float g_ctx[SQ*NHEAD*HD];
__device__ float g_resid1[SQ*HDIM];
__device__ float g_xn2[SQ*HDIM];
__device__ float g_rlog[SQ*NE];
__device__ int   g_tok2e[SQ*2];
__device__ float g_tok2w[SQ*2];
__device__ int   g_tok2row[SQ*2];
__device__ int   g_rows[SQ*2];
__device__ int   g_cnt[NE];
__device__ int   g_off[NE+1];
__device__ int   g_cur[NE];
__device__ float g_xg[SQ*2*HDIM];
__device__ float g_b1[SQ*2*IDIM];
__device__ float g_b3[SQ*2*IDIM];
__device__ float g_y[SQ*2*HDIM];
__device__ int   g_pos64;
__device__ float g_posf[SQ];

// tf32 round-to-nearest
__device__ __forceinline__ float f2tf32rn(float f) {
    unsigned r;
    asm("cvt.rna.tf32.f32 %0, %1;" : "=r"(r) : "f"(f));
    return __uint_as_float(r);
}

// B-operand arrives raw via cp.async -> HW tf32-truncates (multiplicative mean
// shrink ~3.52e-4). Compensate the accumulator once in the epilogue.
#define TRUNC_COMP 1.000352f

// ------------------------- position width detection -------------------------
__global__ void posdetect_kernel(const unsigned int* __restrict__ p) {
    __shared__ int ok;
    if (threadIdx.x == 0) ok = 1;
    __syncthreads();
    int bad = 0;
    for (int i = threadIdx.x; i < SQ/2; i += blockDim.x)
        if (p[2*i+1] != 0u) bad = 1;
    if (bad) atomicAnd(&ok, 0);
    __syncthreads();
    if (threadIdx.x == 0) g_pos64 = ok;
}

__global__ void posconv_kernel(const void* __restrict__ p) {
    int i = blockIdx.x*blockDim.x + threadIdx.x;
    if (i >= SQ) return;
    long long v = g_pos64 ? ((const long long*)p)[i]
                          : (long long)((const int*)p)[i];
    g_posf[i] = (float)v;
}

// ------------------------- RMSNorm -------------------------
__global__ void rmsnorm_kernel(const float* __restrict__ x, const float* __restrict__ w,
                               float* __restrict__ o, int do_round) {
    int row = blockIdx.x;
    const float* xr = x + (size_t)row*HDIM;
    float s = 0.f;
    for (int c = threadIdx.x; c < HDIM; c += blockDim.x) { float v = xr[c]; s += v*v; }
    __shared__ float red[8];
    for (int off = 16; off; off >>= 1) s += __shfl_xor_sync(0xffffffffu, s, off);
    int warp = threadIdx.x >> 5, lane = threadIdx.x & 31;
    if (lane == 0) red[warp] = s;
    __syncthreads();
    if (warp == 0) {
        float t = (lane < 8) ? red[lane] : 0.f;
        for (int off = 4; off; off >>= 1) t += __shfl_xor_sync(0xffffffffu, t, off);
        if (lane == 0) red[0] = t;
    }
    __syncthreads();
    float inv = rsqrtf(red[0] / (float)HDIM + 1e-5f);
    float* orow = o + (size_t)row*HDIM;
    if (do_round) {
        for (int c = threadIdx.x; c < HDIM; c += blockDim.x)
            orow[c] = f2tf32rn(xr[c] * inv * w[c]);
    } else {
        for (int c = threadIdx.x; c < HDIM; c += blockDim.x)
            orow[c] = xr[c] * inv * w[c];
    }
}

// ------------------------- TF32 HMMA GEMM (NT), cp.async 4-stage -------------------------
// C[M,N] = A[M,K] @ B[N,K]^T (+R).  A pre-rounded tf32 by producer (exact under
// HW truncation); B raw (truncated by MMA, compensated in epilogue).
// smem: plain row-major 128 rows x 16 floats (64B/row) per operand per stage.
// k-slot remap: lane tig's fragment = physical k {4tig..4tig+3}; consistent for
// A and B, so contiguous float4 chunks ARE the fragments (1 LDS.128 / frag / BK16).
#define BM 128
#define BN 128
#define BK 16
#define STAGEB 16384           // bytes per stage (A 8KB + B 8KB)
#define NSTAGE 4
#define SMEMTC (NSTAGE*STAGEB)

__device__ __forceinline__ void mma_tf32(float c[4], float2 alo, float2 ahi, float2 b) {
    asm volatile(
        "mma.sync.aligned.m16n8k8.row.col.f32.tf32.tf32.f32 "
        "{%0,%1,%2,%3}, {%4,%5,%6,%7}, {%8,%9}, {%0,%1,%2,%3};\n"
        : "+f"(c[0]), "+f"(c[1]), "+f"(c[2]), "+f"(c[3])
        : "r"(__float_as_uint(alo.x)), "r"(__float_as_uint(ahi.x)),
          "r"(__float_as_uint(alo.y)), "r"(__float_as_uint(ahi.y)),
          "r"(__float_as_uint(b.x)),   "r"(__float_as_uint(b.y)));
}

__device__ __forceinline__ unsigned smem_u32(const void* p) {
    unsigned a;
    asm("{ .reg .u64 t; cvta.to.shared.u64 t, %1; cvt.u32.u64 %0, t; }" : "=r"(a) : "l"(p));
    return a;
}

__device__ __forceinline__ void cpa16(unsigned dst, const float* src, int bytes) {
    asm volatile("cp.async.cg.shared.global [%0], [%1], 16, %2;"
                 :: "r"(dst), "l"(src), "r"(bytes) : "memory");
}
__device__ __forceinline__ void cpa_commit() {
    asm volatile("cp.async.commit_group;" ::: "memory");
}
__device__ __forceinline__ void cpa_wait2() {
    asm volatile("cp.async.wait_group 2;" ::: "memory");
}

__device__ __forceinline__ void tcga_issue(
    unsigned sbase, const float* __restrict__ A, const float* __restrict__ B,
    int m0, int Mend, int n0, int N, int K, int ks, int tid)
{
#pragma unroll
    for (int i = 0; i < 4; i++) {
        int idx = tid + i*256;
        int isB = idx >> 9;           // 0: A-chunk, 1: B-chunk
        int l = idx & 511;
        int r = l >> 2, c = l & 3;
        const float* src;
        int bytes;
        if (!isB) { src = A + (size_t)(m0 + r)*K + ks + (c << 2); bytes = (m0 + r < Mend) ? 16 : 0; }
        else      { src = B + (size_t)(n0 + r)*K + ks + (c << 2); bytes = (n0 + r < N)    ? 16 : 0; }
        unsigned dst = sbase + (isB ? 8192u : 0u) + (unsigned)(r*64 + c*16);
        cpa16(dst, src, bytes);
    }
}

__device__ __forceinline__ void gemm_tf32_body(
    const float* __restrict__ A, const float* __restrict__ B,
    float* __restrict__ C, const float* __restrict__ R,
    int m0, int Mend, int n0, int N, int K)
{
    extern __shared__ float smtc[];
    unsigned sb0 = smem_u32(smtc);
    int tid = threadIdx.x;
    int lane = tid & 31, wid = tid >> 5;
    int wm = (wid & 1) * 64;       // 2 warps over M
    int wn = (wid >> 1) * 32;      // 4 warps over N
    int tig = lane & 3, grp = lane >> 2;

    float acc[4][4][4];
#pragma unroll
    for (int i = 0; i < 4; i++)
#pragma unroll
        for (int j = 0; j < 4; j++)
#pragma unroll
            for (int r = 0; r < 4; r++) acc[i][j][r] = 0.f;

    int nT = K / BK;

    // prologue: stages 0..2
#pragma unroll
    for (int s = 0; s < 3; s++) {
        tcga_issue(sb0 + s*STAGEB, A, B, m0, Mend, n0, N, K, s*BK, tid);
        cpa_commit();
    }

    for (int t = 0; t < nT; t++) {
        cpa_wait2();               // stage t landed (3 groups pending -> <=2)
        __syncthreads();
        const float* sA = smtc + (size_t)(t & 3) * (STAGEB/4);
        const float* sB = sA + 2048;

        float4 bq[4];
#pragma unroll
        for (int j = 0; j < 4; j++)
            bq[j] = *(const float4*)&sB[(wn + j*8 + grp)*16 + tig*4];
#pragma unroll
        for (int i = 0; i < 4; i++) {
            int ra = (wm + i*16 + grp)*16 + tig*4;
            float4 alo = *(const float4*)&sA[ra];
            float4 ahi = *(const float4*)&sA[ra + 8*16];
#pragma unroll
            for (int j = 0; j < 4; j++) {
                mma_tf32(acc[i][j], make_float2(alo.x, alo.y),
                         make_float2(ahi.x, ahi.y), make_float2(bq[j].x, bq[j].y));
                mma_tf32(acc[i][j], make_float2(alo.z, alo.w),
                         make_float2(ahi.z, ahi.w), make_float2(bq[j].z, bq[j].w));
            }
        }

        if (t + 3 < nT)
            tcga_issue(sb0 + ((t + 3) & 3)*STAGEB, A, B, m0, Mend, n0, N, K, (t + 3)*BK, tid);
        cpa_commit();              // unconditional: keeps pending-group count = 3
    }

    // epilogue (B-truncation compensation)
#pragma unroll
    for (int i = 0; i < 4; i++) {
#pragma unroll
        for (int j = 0; j < 4; j++) {
            int row = m0 + wm + i*16 + grp;
            int col = n0 + wn + j*8 + tig*2;
            if (col < N) {
                if (row < Mend) {
                    float2 v = make_float2(acc[i][j][0]*TRUNC_COMP, acc[i][j][1]*TRUNC_COMP);
                    if (R) { v.x += R[(size_t)row*N + col]; v.y += R[(size_t)row*N + col+1]; }
                    *(float2*)(C + (size_t)row*N + col) = v;
                }
                if (row + 8 < Mend) {
                    float2 v = make_float2(acc[i][j][2]*TRUNC_COMP, acc[i][j][3]*TRUNC_COMP);
                    if (R) { v.x += R[(size_t)(row+8)*N + col]; v.y += R[(size_t)(row+8)*N + col+1]; }
                    *(float2*)(C + (size_t)(row+8)*N + col) = v;
                }
            }
        }
    }
}

__global__ __launch_bounds__(256, 2) void gemm_tf32_kernel(
    const float* __restrict__ A, const float* __restrict__ B,
    float* __restrict__ C, const float* __restrict__ R, int M, int N, int K) {
    gemm_tf32_body(A, B, C, R, blockIdx.y*BM, M, blockIdx.x*BN, N, K);
}

__global__ __launch_bounds__(256, 2) void gemm_qkv_kernel(
    const float* __restrict__ A,
    const float* __restrict__ wq, const float* __restrict__ wk, const float* __restrict__ wv) {
    int nb = blockIdx.x;
    const float* B; float* C; int n0, N;
    if (nb < 16)      { B = wq; C = g_q; n0 = nb*BN;       N = NHEAD*HD; }
    else if (nb < 20) { B = wk; C = g_k; n0 = (nb-16)*BN;  N = NKVH*HD;  }
    else              { B = wv; C = g_v; n0 = (nb-20)*BN;  N = NKVH*HD;  }
    gemm_tf32_body(A, B, C, nullptr, blockIdx.y*BM, SQ, n0, N, HDIM);
}

__global__ __launch_bounds__(256, 2) void gemm_tf32_group_kernel(
    const float* __restrict__ A, const float* __restrict__ Ball,
    float* __restrict__ C, int N, int K) {
    int e = blockIdx.z;
    int mstart = g_off[e], mend = g_off[e+1];
    int m0 = mstart + blockIdx.y*BM;
    if (m0 >= mend) return;
    gemm_tf32_body(A, Ball + (size_t)e*N*K, C, nullptr, m0, mend, blockIdx.x*BN, N, K);
}

// ------------------------- RoPE (in-place, outputs tf32-rounded) -------------------------
__global__ void rope_kernel(float* __restrict__ q, float* __restrict__ k) {
    int s  = blockIdx.x;
    int hh = blockIdx.y;
    int d2 = threadIdx.x;   // 0..31
    float* p;
    if (hh < NHEAD) p = q + (size_t)s*(NHEAD*HD) + hh*HD;
    else            p = k + (size_t)s*(NKVH*HD) + (hh-NHEAD)*HD;
    float ps = g_posf[s];
    float inv = exp2f(-(float)d2 * 0.41524101186092029f);
    float ang = ps * inv;
    float sn, cs;
    sincosf(ang, &sn, &cs);
    float x1 = p[d2], x2 = p[d2+32];
    p[d2]    = f2tf32rn(x1*cs - x2*sn);
    p[d2+32] = f2tf32rn(x2*cs + x1*sn);
}

// ------------------------- Flash attention on tf32 mma.sync (round-9, proven) ----
#define AQT 128
#define AKT 32

__global__ __launch_bounds__(256) void attn_mma_kernel(
    const float* __restrict__ q, const float* __restrict__ k,
    const float* __restrict__ v, float* __restrict__ ctx)
{
    __shared__ float sm[8192];
    int bq = blockIdx.x, h = blockIdx.y;
    int kvh = h >> 2;
    int q0 = bq * AQT;
    int tid = threadIdx.x, wid = tid >> 5, lane = tid & 31;
    int tig = lane & 3, grp = lane >> 2;

#pragma unroll
    for (int i = 0; i < 8; i++) {
        int fid = tid + i*256;
        int row = fid >> 4, c4 = fid & 15;
        float4 vq = *(const float4*)(q + (size_t)(q0+row)*(NHEAD*HD) + h*HD + (c4 << 2));
        int g = c4 >> 2, sw = (row & 3) ^ ((row >> 2) & 1);
        float* d = &sm[row*64 + g*16 + (c4 & 3)];
        d[((0^sw)<<2)] = vq.x; d[((1^sw)<<2)] = vq.y;
        d[((2^sw)<<2)] = vq.z; d[((3^sw)<<2)] = vq.w;
    }
    __syncthreads();
    int r0 = wid*16 + grp;
    int swA = (grp & 3) ^ ((grp >> 2) & 1);
    int chA = ((tig ^ swA) << 2);
    float4 qf0[4], qf1[4];
#pragma unroll
    for (int g = 0; g < 4; g++) {
        qf0[g] = *(const float4*)&sm[r0*64 + g*16 + chA];
        qf1[g] = *(const float4*)&sm[(r0+8)*64 + g*16 + chA];
    }
    __syncthreads();

    int qrow0 = q0 + r0, qrow1 = qrow0 + 8;
    float m0 = -INFINITY, m1 = -INFINITY, l0 = 0.f, l1 = 0.f;
    float oa[8][4];
#pragma unroll
    for (int j = 0; j < 8; j++)
#pragma unroll
        for (int r = 0; r < 4; r++) oa[j][r] = 0.f;

    float* pslab = &sm[4096 + wid*512];
    int chP = chA;

    int nkt = 4*bq + 4;
    for (int kt = 0; kt < nkt; kt++) {
#pragma unroll
        for (int i = 0; i < 2; i++) {
            int fid = tid + i*256;
            int row = fid >> 4, c4 = fid & 15;
            size_t goff = (size_t)(kt*AKT + row)*(NKVH*HD) + kvh*HD + (c4 << 2);
            float4 kv4 = *(const float4*)(k + goff);
            int g = c4 >> 2, sw = (row & 3) ^ ((row >> 2) & 1);
            float* d = &sm[row*64 + g*16 + (c4 & 3)];
            d[((0^sw)<<2)] = kv4.x; d[((1^sw)<<2)] = kv4.y;
            d[((2^sw)<<2)] = kv4.z; d[((3^sw)<<2)] = kv4.w;
            float4 vv4 = *(const float4*)(v + goff);
            float vals[4] = {vv4.x, vv4.y, vv4.z, vv4.w};
            int k16 = row & 15;
            int cbase = (row >> 4)*16 + (k16 >> 2);
#pragma unroll
            for (int e = 0; e < 4; e++) {
                int dp = (c4 << 2) + e;
                int sw2 = (dp & 3) ^ ((dp >> 2) & 1);
                sm[2048 + dp*32 + cbase + (((k16 & 3) ^ sw2) << 2)] = f2tf32rn(vals[e]);
            }
        }
        __syncthreads();

        float sc[4][4];
#pragma unroll
        for (int j = 0; j < 4; j++)
#pragma unroll
            for (int r = 0; r < 4; r++) sc[j][r] = 0.f;
#pragma unroll
        for (int j = 0; j < 4; j++) {
            int krow = j*8 + grp;
            int swB = (krow & 3) ^ ((krow >> 2) & 1);
            int chB = ((tig ^ swB) << 2);
#pragma unroll
            for (int g = 0; g < 4; g++) {
                float4 bf = *(const float4*)&sm[krow*64 + g*16 + chB];
                mma_tf32(sc[j], make_float2(qf0[g].x, qf0[g].y),
                         make_float2(qf1[g].x, qf1[g].y), make_float2(bf.x, bf.y));
                mma_tf32(sc[j], make_float2(qf0[g].z, qf0[g].w),
                         make_float2(qf1[g].z, qf1[g].w), make_float2(bf.z, bf.w));
            }
        }

        float lm0 = -INFINITY, lm1 = -INFINITY;
#pragma unroll
        for (int j = 0; j < 4; j++) {
            int col = kt*AKT + j*8 + 2*tig;
            sc[j][0] = (col     <= qrow0) ? sc[j][0]*0.125f : -1e30f;
            sc[j][1] = (col + 1 <= qrow0) ? sc[j][1]*0.125f : -1e30f;
            sc[j][2] = (col     <= qrow1) ? sc[j][2]*0.125f : -1e30f;
            sc[j][3] = (col + 1 <= qrow1) ? sc[j][3]*0.125f : -1e30f;
            lm0 = fmaxf(lm0, fmaxf(sc[j][0], sc[j][1]));
            lm1 = fmaxf(lm1, fmaxf(sc[j][2], sc[j][3]));
        }
        lm0 = fmaxf(lm0, __shfl_xor_sync(0xffffffffu, lm0, 1));
        lm0 = fmaxf(lm0, __shfl_xor_sync(0xffffffffu, lm0, 2));
        lm1 = fmaxf(lm1, __shfl_xor_sync(0xffffffffu, lm1, 1));
        lm1 = fmaxf(lm1, __shfl_xor_sync(0xffffffffu, lm1, 2));
        float mn0 = fmaxf(m0, lm0), mn1 = fmaxf(m1, lm1);
        float s0 = __expf(m0 - mn0), s1 = __expf(m1 - mn1);
        float ps0 = 0.f, ps1 = 0.f;
#pragma unroll
        for (int j = 0; j < 4; j++) {
            sc[j][0] = __expf(sc[j][0] - mn0);
            sc[j][1] = __expf(sc[j][1] - mn0);
            sc[j][2] = __expf(sc[j][2] - mn1);
            sc[j][3] = __expf(sc[j][3] - mn1);
            ps0 += sc[j][0] + sc[j][1];
            ps1 += sc[j][2] + sc[j][3];
        }
        ps0 += __shfl_xor_sync(0xffffffffu, ps0, 1);
        ps0 += __shfl_xor_sync(0xffffffffu, ps0, 2);
        ps1 += __shfl_xor_sync(0xffffffffu, ps1, 1);
        ps1 += __shfl_xor_sync(0xffffffffu, ps1, 2);
        l0 = l0*s0 + ps0; l1 = l1*s1 + ps1;
        m0 = mn0; m1 = mn1;
#pragma unroll
        for (int j = 0; j < 8; j++) {
            oa[j][0] *= s0; oa[j][1] *= s0;
            oa[j][2] *= s1; oa[j][3] *= s1;
        }

#pragma unroll
        for (int j = 0; j < 4; j++) {
            int g2 = j >> 1;
            int k16a = (j & 1)*8 + 2*tig;
            int k16b = k16a + 1;
            int c0 = g2*16 + (((k16a & 3) ^ swA) << 2) + (k16a >> 2);
            int c1 = g2*16 + (((k16b & 3) ^ swA) << 2) + (k16b >> 2);
            pslab[grp*32 + c0]     = f2tf32rn(sc[j][0]);
            pslab[grp*32 + c1]     = f2tf32rn(sc[j][1]);
            pslab[(grp+8)*32 + c0] = f2tf32rn(sc[j][2]);
            pslab[(grp+8)*32 + c1] = f2tf32rn(sc[j][3]);
        }
        __syncwarp();
        float4 pf0[2], pf1[2];
#pragma unroll
        for (int g = 0; g < 2; g++) {
            pf0[g] = *(const float4*)&pslab[grp*32 + g*16 + chP];
            pf1[g] = *(const float4*)&pslab[(grp+8)*32 + g*16 + chP];
        }

#pragma unroll
        for (int jd = 0; jd < 8; jd++) {
            int vrow = jd*8 + grp;
            int swV = (vrow & 3) ^ ((vrow >> 2) & 1);
            int chV = ((tig ^ swV) << 2);
#pragma unroll
            for (int g = 0; g < 2; g++) {
                float4 bf = *(const float4*)&sm[2048 + vrow*32 + g*16 + chV];
                mma_tf32(oa[jd], make_float2(pf0[g].x, pf0[g].y),
                         make_float2(pf1[g].x, pf1[g].y), make_float2(bf.x, bf.y));
                mma_tf32(oa[jd], make_float2(pf0[g].z, pf0[g].w),
                         make_float2(pf1[g].z, pf1[g].w), make_float2(bf.z, bf.w));
            }
        }
        __syncthreads();
    }

    float rl0 = 1.f / l0, rl1 = 1.f / l1;
#pragma unroll
    for (int jd = 0; jd < 8; jd++) {
        int dcol = jd*8 + 2*tig;
        float2 v0 = make_float2(f2tf32rn(oa[jd][0]*rl0), f2tf32rn(oa[jd][1]*rl0));
        float2 v1 = make_float2(f2tf32rn(oa[jd][2]*rl1), f2tf32rn(oa[jd][3]*rl1));
        *(float2*)(ctx + (size_t)qrow0*(NHEAD*HD) + h*HD + dcol) = v0;
        *(float2*)(ctx + (size_t)qrow1*(NHEAD*HD) + h*HD + dcol) = v1;
    }
}

// ------------------------- MoE routing -------------------------
__global__ void reset_kernel() {
    int i = threadIdx.x;
    if (i < NE) { g_cnt[i] = 0; g_cur[i] = 0; }
}

__global__ void router_kernel(const float* __restrict__ x, const float* __restrict__ wg) {
    int t = blockIdx.x;
    int warp = threadIdx.x >> 5, lane = threadIdx.x & 31;
    const float* xr = x + (size_t)t*HDIM;
    const float* wr = wg + (size_t)warp*HDIM;
    float s = 0.f;
    for (int c = lane; c < HDIM; c += 32) s += xr[c]*wr[c];
    for (int off = 16; off; off >>= 1) s += __shfl_xor_sync(0xffffffffu, s, off);
    __shared__ float lg[NE];
    if (lane == 0) lg[warp] = s;
    __syncthreads();
    if (threadIdx.x == 0) {
        int i0 = 0;
        for (int e = 1; e < NE; e++) if (lg[e] > lg[i0]) i0 = e;
        int i1 = (i0 == 0) ? 1 : 0;
        for (int e = 0; e < NE; e++) { if (e == i0) continue; if (lg[e] > lg[i1]) i1 = e; }
        float w0 = 1.f / (1.f + __expf(lg[i1] - lg[i0]));
        for (int e = 0; e < NE; e++) g_rlog[t*NE + e] = lg[e];
        g_tok2e[t*2]   = i0; g_tok2e[t*2+1] = i1;
        g_tok2w[t*2]   = w0; g_tok2w[t*2+1] = 1.f - w0;
        atomicAdd(&g_cnt[i0], 1);
        atomicAdd(&g_cnt[i1], 1);
    }
}

__global__ void scan_kernel() {
    if (threadIdx.x == 0) {
        int acc = 0;
        for (int e = 0; e < NE; e++) { g_off[e] = acc; acc += g_cnt[e]; }
        g_off[NE] = acc;
    }
}

__global__ void scatter_kernel() {
    int t = blockIdx.x*blockDim.x + threadIdx.x;
    if (t >= SQ) return;
#pragma unroll
    for (int sl = 0; sl < 2; sl++) {
        int e = g_tok2e[t*2+sl];
        int rrel = atomicAdd(&g_cur[e], 1);
        int rr = g_off[e] + rrel;
        g_rows[rr] = t;
        g_tok2row[t*2+sl] = rr;
    }
}

__global__ void gather_kernel() {
    int total = SQ*2*(HDIM/4);
    for (int idx = blockIdx.x*blockDim.x + threadIdx.x; idx < total; idx += gridDim.x*blockDim.x) {
        int row = idx / (HDIM/4);
        int c4  = idx % (HDIM/4);
        float4 v = ((const float4*)g_xn2)[(size_t)g_rows[row]*(HDIM/4) + c4];
        v.x = f2tf32rn(v.x); v.y = f2tf32rn(v.y);
        v.z = f2tf32rn(v.z); v.w = f2tf32rn(v.w);
        ((float4*)g_xg)[(size_t)row*(HDIM/4) + c4] = v;
    }
}

__global__ void silu_kernel() {
    size_t total = (size_t)SQ*2*IDIM;
    for (size_t i = blockIdx.x*(size_t)blockDim.x + threadIdx.x; i < total;
         i += (size_t)gridDim.x*blockDim.x) {
        float x = g_b1[i];
        float g = x / (1.f + __expf(-x));
        g_b1[i] = f2tf32rn(g * g_b3[i]);
    }
}

__global__ void finalize_kernel(const float* __restrict__ resid, float* __restrict__ out) {
    int t = blockIdx.x;
    int r0 = g_tok2row[t*2], r1 = g_tok2row[t*2+1];
    float w0 = g_tok2w[t*2], w1 = g_tok2w[t*2+1];
    for (int c = threadIdx.x; c < HDIM; c += blockDim.x) {
        out[(size_t)t*HDIM + c] = resid[(size_t)t*HDIM + c]
            + w0*g_y[(size_t)r0*HDIM + c] + w1*g_y[(size_t)r1*HDIM + c];
    }
}

// ------------------------- output tail writers -------------------------
__global__ void gate_kernel(float* __restrict__ dst, const float* __restrict__ gin) {
    int i = blockIdx.x*blockDim.x + threadIdx.x;
    int total = 4*SQ*NE;
    if (i < total) dst[i] = (i < SQ*NE) ? g_rlog[i] : gin[i];
}

__global__ void posf_kernel(float* __restrict__ dst, int n) {
    int i = blockIdx.x*blockDim.x + threadIdx.x;
    if (i < n) dst[i] = g_posf[i];
}

__global__ void posraw_kernel(float* __restrict__ dst, int n) {
    int i = blockIdx.x*blockDim.x + threadIdx.x;
    if (i < n) ((long long*)dst)[i] = (long long)g_posf[i];
}

__global__ void zerofill_kernel(float* __restrict__ dst, int n) {
    int i = blockIdx.x*blockDim.x + threadIdx.x;
    if (i < n) dst[i] = 0.f;
}

// ------------------------- launch -------------------------
extern "C" void kernel_launch(void* const* d_in, const int* in_sizes, int n_in,
                              void* d_out, int out_size) {
    const float* hidden = (const float*)d_in[0];
    const void*  posraw = d_in[1];
    const float* gatein = (const float*)d_in[2];
    const float* ln1 = (const float*)d_in[3];
    const float* ln2 = (const float*)d_in[4];
    const float* wq  = (const float*)d_in[5];
    const float* wk  = (const float*)d_in[6];
    const float* wv  = (const float*)d_in[7];
    const float* wo  = (const float*)d_in[8];
    const float* wg  = (const float*)d_in[9];
    const float* w1  = (const float*)d_in[10];
    const float* w2  = (const float*)d_in[11];
    const float* w3  = (const float*)d_in[12];

    float *xn1,*q,*k,*v,*ctx,*resid1,*xn2,*xg,*b1,*b3,*y;
    cudaGetSymbolAddress((void**)&xn1,    g_xn1);
    cudaGetSymbolAddress((void**)&q,      g_q);
    cudaGetSymbolAddress((void**)&k,      g_k);
    cudaGetSymbolAddress((void**)&v,      g_v);
    cudaGetSymbolAddress((void**)&ctx,    g_ctx);
    cudaGetSymbolAddress((void**)&resid1, g_resid1);
    cudaGetSymbolAddress((void**)&xn2,    g_xn2);
    cudaGetSymbolAddress((void**)&xg,     g_xg);
    cudaGetSymbolAddress((void**)&b1,     g_b1);
    cudaGetSymbolAddress((void**)&b3,     g_b3);
    cudaGetSymbolAddress((void**)&y,      g_y);

    cudaFuncSetAttribute(gemm_tf32_kernel,       cudaFuncAttributeMaxDynamicSharedMemorySize, SMEMTC);
    cudaFuncSetAttribute(gemm_qkv_kernel,        cudaFuncAttributeMaxDynamicSharedMemorySize, SMEMTC);
    cudaFuncSetAttribute(gemm_tf32_group_kernel, cudaFuncAttributeMaxDynamicSharedMemorySize, SMEMTC);

    posdetect_kernel<<<1, 256>>>((const unsigned int*)posraw);
    posconv_kernel<<<SQ/256, 256>>>(posraw);

    // attention path
    rmsnorm_kernel<<<SQ, 256>>>(hidden, ln1, xn1, 1);
    gemm_qkv_kernel<<<dim3(24, SQ/BM), 256, SMEMTC>>>(xn1, wq, wk, wv);
    rope_kernel<<<dim3(SQ, NHEAD+NKVH), 32>>>(q, k);
    attn_mma_kernel<<<dim3(SQ/AQT, NHEAD), 256>>>(q, k, v, ctx);
    dim3 gq(HDIM/BN, SQ/BM);
    gemm_tf32_kernel<<<gq, 256, SMEMTC>>>(ctx, wo, resid1, hidden, SQ, HDIM, HDIM);

    // MoE path
    rmsnorm_kernel<<<SQ, 256>>>(resid1, ln2, xn2, 0);
    reset_kernel<<<1, 32>>>();
    router_kernel<<<SQ, 256>>>(xn2, wg);
    scan_kernel<<<1, 32>>>();
    scatter_kernel<<<SQ/256, 256>>>();
    gather_kernel<<<512, 256>>>();
    gemm_tf32_group_kernel<<<dim3(IDIM/BN, SQ/BM, NE), 256, SMEMTC>>>(xg, w1, b1, IDIM, HDIM);
    gemm_tf32_group_kernel<<<dim3(IDIM/BN, SQ/BM, NE), 256, SMEMTC>>>(xg, w3, b3, IDIM, HDIM);
    silu_kernel<<<2048, 256>>>();
    gemm_tf32_group_kernel<<<dim3(HDIM/BN, SQ/BM, NE), 256, SMEMTC>>>(b1, w2, y, HDIM, IDIM);

    float* out = (float*)d_out;
    const int HTOT = SQ*HDIM;
    const int GTOT = 4*SQ*NE;
    finalize_kernel<<<SQ, 256>>>(resid1, out);

    int rem = out_size - HTOT;
    if (rem >= GTOT) {
        gate_kernel<<<(GTOT+255)/256, 256>>>(out + (out_size - GTOT), gatein);
        rem -= GTOT;
    }
    if (rem == SQ) {
        posf_kernel<<<(SQ+255)/256, 256>>>(out + HTOT, SQ);
    } else if (rem == 2*SQ) {
        posraw_kernel<<<(SQ+255)/256, 256>>>(out + HTOT, SQ);
    } else if (rem > 0) {
        zerofill_kernel<<<(rem+255)/256, 256>>>(out + HTOT, rem);
    }
}